// round 7
// baseline (speedup 1.0000x reference)
#include <cuda_runtime.h>
#include <math.h>
#include <stdint.h>

// Problem sizes (fixed by the dataset)
#define NN 100000
#define EE 500000

// Scratch (device globals; allocation-free per harness rules)
__device__ float g_cnt[NN];
__device__ float g_sum1[(size_t)NN * 128];
__device__ float g_sum2[(size_t)NN * 128];
__device__ float g_proj[(size_t)NN * 128];
__device__ float g_srcF[(size_t)EE * 128];
__device__ float g_dstF[(size_t)EE * 128];

__device__ __forceinline__ float4 ldg4(const float* p) {
    return __ldg((const float4*)p);
}

__device__ __forceinline__ void red4(float* p, float4 v) {
    asm volatile("red.global.add.v4.f32 [%0], {%1,%2,%3,%4};"
                 :: "l"(p), "f"(v.x), "f"(v.y), "f"(v.z), "f"(v.w) : "memory");
}
__device__ __forceinline__ void red2(float* p, float2 v) {
    asm volatile("red.global.add.v2.f32 [%0], {%1,%2};"
                 :: "l"(p), "f"(v.x), "f"(v.y) : "memory");
}

// fp32 -> tf32 (round to nearest)
__device__ __forceinline__ uint32_t f2tf(float f) {
    uint32_t u;
    asm("cvt.rna.tf32.f32 %0, %1;" : "=r"(u) : "f"(f));
    return u;
}

// D += A(16x8) * B(8x8), tf32 inputs, f32 accum
__device__ __forceinline__ void mma8(float* c, const uint32_t* a, const uint32_t* b) {
    asm volatile(
        "mma.sync.aligned.m16n8k8.row.col.f32.tf32.tf32.f32 "
        "{%0,%1,%2,%3}, {%4,%5,%6,%7}, {%8,%9}, {%0,%1,%2,%3};"
        : "+f"(c[0]), "+f"(c[1]), "+f"(c[2]), "+f"(c[3])
        : "r"(a[0]), "r"(a[1]), "r"(a[2]), "r"(a[3]), "r"(b[0]), "r"(b[1]));
}

// Load A fragment (m16 x k8) from swizzled smem tile.
// swizzle: element (r, c) stored at col c ^ ((r&7)<<2). stride % 32 == 0.
__device__ __forceinline__ void ldA(uint32_t a[4], const uint32_t* As, int stride,
                                    int rowBase, int k0, int g, int t4) {
    int key = g << 2;
    const uint32_t* p0 = As + (size_t)(rowBase + g) * stride;
    const uint32_t* p1 = p0 + (size_t)8 * stride;
    int c0 = (k0 + t4) ^ key;
    int c1 = (k0 + 4 + t4) ^ key;
    a[0] = p0[c0];
    a[1] = p1[c0];
    a[2] = p0[c1];
    a[3] = p1[c1];
}

// Stage 16 rows x 128 cols of W (row-major) into fragment-packed layout:
// word [(ks2*16 + nt)*32 + lane]*2 + s  <- W[ks2*8 + s*4 + t4][nt*8 + g], lane = g*4+t4
__device__ __forceinline__ void fillW(const float* __restrict__ Wrows, uint32_t* Wf, int tid) {
    for (int i = tid; i < 512; i += 128) {
        int rr = i >> 5, cq = (i & 31) * 4;
        float4 w = ldg4(&Wrows[(size_t)rr * 128 + cq]);
        int ks2 = rr >> 3, s = (rr >> 2) & 1, tt = rr & 3;
        int nt = cq >> 3, gg = cq & 7;
        uint32_t* dst = &Wf[((ks2 * 16 + nt) * 32 + tt) * 2 + s];
        dst[(gg + 0) * 8] = f2tf(w.x);
        dst[(gg + 1) * 8] = f2tf(w.y);
        dst[(gg + 2) * 8] = f2tf(w.z);
        dst[(gg + 3) * 8] = f2tf(w.w);
    }
}

#define WF_WORDS 2048  // 2 ksteps * 16 ntiles * 32 lanes * 2

// ---------------------------------------------------------------------------
// Zero cnt + sum1 + sum2
// ---------------------------------------------------------------------------
__global__ void k_zero(float* cnt, float* s1, float* s2, int n) {
    int i = blockIdx.x * blockDim.x + threadIdx.x;
    int stride = gridDim.x * blockDim.x;
    int t4 = n * 32;
    float4 z = make_float4(0.f, 0.f, 0.f, 0.f);
    for (int j = i; j < t4; j += stride) {
        ((float4*)s1)[j] = z;
        ((float4*)s2)[j] = z;
    }
    for (int j = i; j < n; j += stride) cnt[j] = 0.f;
}

// ---------------------------------------------------------------------------
// Layer-1 aggregation (L2 atomics)
// ---------------------------------------------------------------------------
__global__ void k_agg1(const float* __restrict__ nfeat, const float* __restrict__ efeat,
                       const int* __restrict__ src, const int* __restrict__ dst,
                       float* sum1, float* cnt, int E) {
    int warp = (blockIdx.x * blockDim.x + threadIdx.x) >> 5;
    int lane = threadIdx.x & 31;
    int nw = (gridDim.x * blockDim.x) >> 5;
    for (int e = warp; e < E; e += nw) {
        int s = __ldg(&src[e]);
        int d = __ldg(&dst[e]);
        float4 vs, vd;
        int off;
        if (lane < 16) {
            off = lane * 4;
            vs = ldg4(&nfeat[(size_t)d * 64 + off]);
            vd = ldg4(&nfeat[(size_t)s * 64 + off]);
        } else {
            int q = (lane - 16) * 4;
            off = 64 + q;
            float4 ef = ldg4(&efeat[(size_t)e * 64 + q]);
            vs = ef; vd = ef;
        }
        red4(&sum1[(size_t)s * 128 + off], vs);
        red4(&sum1[(size_t)d * 128 + off], vd);
        if (lane == 0) {
            atomicAdd(&cnt[s], 1.f);
            atomicAdd(&cnt[d], 1.f);
        }
    }
}

// ---------------------------------------------------------------------------
// Tensor-core node projection: proj[n] = (sum[n]/max(cnt,1)) @ W[128,128] + b
// Block: 128 threads / 4 warps / 32 nodes. Warp tile 32x32.
// ---------------------------------------------------------------------------
__global__ __launch_bounds__(128, 3) void k_proj_t(
    const float* __restrict__ sum, const float* __restrict__ cnt,
    const float* __restrict__ W, const float* __restrict__ bias,
    float* __restrict__ proj, int Nn) {
    extern __shared__ uint32_t sm[];
    uint32_t* As = sm;                 // 32*128 words
    uint32_t* Wf = sm + 32 * 128;      // WF_WORDS
    __shared__ float invS[32];
    int tid = threadIdx.x, lane = tid & 31, warp = tid >> 5;
    int g = lane >> 2, t4 = lane & 3;
    int n0 = blockIdx.x * 32;
    int ntB = warp * 4;

    if (tid < 32) {
        int n = n0 + tid;
        float c = 1.f;
        if (n < Nn) c = fmaxf(__ldg(&cnt[n]), 1.f);
        invS[tid] = 1.f / c;
    }
    __syncthreads();
    for (int i = tid; i < 32 * 32; i += 128) {
        int r = i >> 5, q = (i & 31) * 4;
        int n = n0 + r;
        float4 v = make_float4(0.f, 0.f, 0.f, 0.f);
        if (n < Nn) v = ldg4(&sum[(size_t)n * 128 + q]);
        float s = invS[r];
        uint4 u;
        u.x = f2tf(v.x * s); u.y = f2tf(v.y * s);
        u.z = f2tf(v.z * s); u.w = f2tf(v.w * s);
        *(uint4*)&As[r * 128 + (q ^ ((r & 7) << 2))] = u;
    }

    float acc[2][4][4];
#pragma unroll
    for (int m = 0; m < 2; m++)
#pragma unroll
        for (int nt = 0; nt < 4; nt++)
#pragma unroll
            for (int k = 0; k < 4; k++) acc[m][nt][k] = 0.f;

    for (int kc = 0; kc < 128; kc += 16) {
        __syncthreads();
        fillW(&W[(size_t)kc * 128], Wf, tid);
        __syncthreads();
#pragma unroll
        for (int ks2 = 0; ks2 < 2; ks2++) {
            int k0 = kc + ks2 * 8;
            uint32_t a[2][4];
            ldA(a[0], As, 128, 0, k0, g, t4);
            ldA(a[1], As, 128, 16, k0, g, t4);
#pragma unroll
            for (int nt = 0; nt < 4; nt++) {
                uint2 bf = *(const uint2*)&Wf[((ks2 * 16 + ntB + nt) * 32 + lane) * 2];
                mma8(acc[0][nt], a[0], (const uint32_t*)&bf);
                mma8(acc[1][nt], a[1], (const uint32_t*)&bf);
            }
        }
    }

#pragma unroll
    for (int m = 0; m < 2; m++)
#pragma unroll
        for (int h = 0; h < 2; h++) {
            int r = m * 16 + h * 8 + g;
            int n = n0 + r;
            if (n < Nn) {
#pragma unroll
                for (int nt = 0; nt < 4; nt++) {
                    int col = (ntB + nt) * 8 + t4 * 2;
                    float2 bb = __ldg((const float2*)&bias[col]);
                    float2 o;
                    o.x = acc[m][nt][h * 2 + 0] + bb.x;
                    o.y = acc[m][nt][h * 2 + 1] + bb.y;
                    *(float2*)&proj[(size_t)n * 128 + col] = o;
                }
            }
        }
}

// ---------------------------------------------------------------------------
// Tensor-core layer-1 edge kernel. Block: 128 thr / 4 warps / 32 edges.
// A (tf32, swizzled, stride 256): [0,64)=nfeat[src], [64,128)=nfeat[dst],
//                                 [128,192)=efeat, [192,256)=te
// W rows: [0,64) head (per src/dst), [64,192) shared.
// ---------------------------------------------------------------------------
__global__ __launch_bounds__(128, 3) void k_layer1_t(
    const float* __restrict__ nfeat, const float* __restrict__ efeat,
    const int* __restrict__ src, const int* __restrict__ dst, const float* __restrict__ ts,
    const float* __restrict__ W, const float* __restrict__ bias,
    const float* __restrict__ omega, const float* __restrict__ phase,
    const float* __restrict__ proj, float* __restrict__ outS, float* __restrict__ outD,
    float* __restrict__ sum2, int E) {
    const int AS = 256;
    extern __shared__ uint32_t sm[];
    uint32_t* A = sm;                  // 32*256 words
    uint32_t* Wf = sm + 32 * 256;      // WF_WORDS
    __shared__ int sI[32], dI[32];
    __shared__ float tsS[32];
    int tid = threadIdx.x, lane = tid & 31, warp = tid >> 5;
    int g = lane >> 2, t4 = lane & 3;
    int e0 = blockIdx.x * 32;
    int ntB = warp * 4;

    if (tid < 32) {
        int e = e0 + tid;
        bool ok = e < E;
        sI[tid] = ok ? __ldg(&src[e]) : 0;
        dI[tid] = ok ? __ldg(&dst[e]) : 0;
        tsS[tid] = ok ? __ldg(&ts[e]) : 0.f;
    }
    __syncthreads();

    // Fill A (48 float4 per edge), converted to tf32, swizzled.
    for (int i = tid; i < 32 * 48; i += 128) {
        int r = i / 48, p = i % 48;
        int e = e0 + r;
        bool ok = e < E;
        float4 v = make_float4(0.f, 0.f, 0.f, 0.f);
        int col;
        if (p < 16) {
            col = p * 4;
            if (ok) v = ldg4(&nfeat[(size_t)sI[r] * 64 + p * 4]);
        } else if (p < 32) {
            col = 64 + (p - 16) * 4;
            if (ok) v = ldg4(&nfeat[(size_t)dI[r] * 64 + (p - 16) * 4]);
        } else {
            col = 128 + (p - 32) * 4;
            if (ok) v = ldg4(&efeat[(size_t)e * 64 + (p - 32) * 4]);
        }
        uint4 u;
        u.x = f2tf(v.x); u.y = f2tf(v.y); u.z = f2tf(v.z); u.w = f2tf(v.w);
        *(uint4*)&A[r * AS + (col ^ ((r & 7) << 2))] = u;
    }
    // te cols [192,256)
    for (int i = tid; i < 32 * 16; i += 128) {
        int r = i >> 4, q = (i & 15) * 4;
        float t = tsS[r];
        uint4 u;
        u.x = f2tf(cosf(t * __ldg(&omega[q + 0]) + __ldg(&phase[q + 0])));
        u.y = f2tf(cosf(t * __ldg(&omega[q + 1]) + __ldg(&phase[q + 1])));
        u.z = f2tf(cosf(t * __ldg(&omega[q + 2]) + __ldg(&phase[q + 2])));
        u.w = f2tf(cosf(t * __ldg(&omega[q + 3]) + __ldg(&phase[q + 3])));
        *(uint4*)&A[r * AS + ((192 + q) ^ ((r & 7) << 2))] = u;
    }

    float accS[2][4][4], accD[2][4][4], accH[2][4][4];
#pragma unroll
    for (int m = 0; m < 2; m++)
#pragma unroll
        for (int nt = 0; nt < 4; nt++)
#pragma unroll
            for (int k = 0; k < 4; k++) {
                accS[m][nt][k] = 0.f; accD[m][nt][k] = 0.f; accH[m][nt][k] = 0.f;
            }

    // Head: W rows [0,64); src = A cols k, dst = A cols 64+k
    for (int kc = 0; kc < 64; kc += 16) {
        __syncthreads();
        fillW(&W[(size_t)kc * 128], Wf, tid);
        __syncthreads();
#pragma unroll
        for (int ks2 = 0; ks2 < 2; ks2++) {
            int k0 = kc + ks2 * 8;
            uint32_t aS4[2][4], aD4[2][4];
            ldA(aS4[0], A, AS, 0, k0, g, t4);
            ldA(aS4[1], A, AS, 16, k0, g, t4);
            ldA(aD4[0], A, AS, 0, 64 + k0, g, t4);
            ldA(aD4[1], A, AS, 16, 64 + k0, g, t4);
#pragma unroll
            for (int nt = 0; nt < 4; nt++) {
                uint2 bf = *(const uint2*)&Wf[((ks2 * 16 + ntB + nt) * 32 + lane) * 2];
                mma8(accS[0][nt], aS4[0], (const uint32_t*)&bf);
                mma8(accS[1][nt], aS4[1], (const uint32_t*)&bf);
                mma8(accD[0][nt], aD4[0], (const uint32_t*)&bf);
                mma8(accD[1][nt], aD4[1], (const uint32_t*)&bf);
            }
        }
    }
    // Shared: W rows [64,192); A cols [128,256)
    for (int kc = 0; kc < 128; kc += 16) {
        __syncthreads();
        fillW(&W[(size_t)(64 + kc) * 128], Wf, tid);
        __syncthreads();
#pragma unroll
        for (int ks2 = 0; ks2 < 2; ks2++) {
            int k0 = 128 + kc + ks2 * 8;
            uint32_t aH4[2][4];
            ldA(aH4[0], A, AS, 0, k0, g, t4);
            ldA(aH4[1], A, AS, 16, k0, g, t4);
#pragma unroll
            for (int nt = 0; nt < 4; nt++) {
                uint2 bf = *(const uint2*)&Wf[((ks2 * 16 + ntB + nt) * 32 + lane) * 2];
                mma8(accH[0][nt], aH4[0], (const uint32_t*)&bf);
                mma8(accH[1][nt], aH4[1], (const uint32_t*)&bf);
            }
        }
    }

    // Epilogue: bias + proj gather + relu; scratch write; fused layer-2 segment-sum
#pragma unroll
    for (int m = 0; m < 2; m++)
#pragma unroll
        for (int h = 0; h < 2; h++) {
            int r = m * 16 + h * 8 + g;
            int e = e0 + r;
            if (e < E) {
                int s = sI[r], d = dI[r];
#pragma unroll
                for (int nt = 0; nt < 4; nt++) {
                    int col = (ntB + nt) * 8 + t4 * 2;
                    float2 bb = __ldg((const float2*)&bias[col]);
                    float2 pS = __ldg((const float2*)&proj[(size_t)s * 128 + col]);
                    float2 pD = __ldg((const float2*)&proj[(size_t)d * 128 + col]);
                    float hx = accH[m][nt][h * 2 + 0], hy = accH[m][nt][h * 2 + 1];
                    float2 os, od;
                    os.x = fmaxf(accS[m][nt][h * 2 + 0] + hx + bb.x + pS.x, 0.f);
                    os.y = fmaxf(accS[m][nt][h * 2 + 1] + hy + bb.y + pS.y, 0.f);
                    od.x = fmaxf(accD[m][nt][h * 2 + 0] + hx + bb.x + pD.x, 0.f);
                    od.y = fmaxf(accD[m][nt][h * 2 + 1] + hy + bb.y + pD.y, 0.f);
                    *(float2*)&outS[(size_t)e * 128 + col] = os;
                    *(float2*)&outD[(size_t)e * 128 + col] = od;
                    red2(&sum2[(size_t)s * 128 + col], od);
                    red2(&sum2[(size_t)d * 128 + col], os);
                }
            }
        }
}

// ---------------------------------------------------------------------------
// Tensor-core layer-2 edge kernel. Block: 128 thr / 4 warps / 32 edges.
// A (tf32, swizzled, stride 320): [0,128)=srcF, [128,256)=dstF, [256,320)=te2
// W rows: [0,128) head, [128,192) te (shared). Writes final output.
// ---------------------------------------------------------------------------
__global__ __launch_bounds__(128, 3) void k_layer2_t(
    const float* __restrict__ fS, const float* __restrict__ fD,
    const int* __restrict__ src, const int* __restrict__ dst, const float* __restrict__ ts,
    const float* __restrict__ W, const float* __restrict__ bias,
    const float* __restrict__ omega, const float* __restrict__ phase,
    const float* __restrict__ proj, float* __restrict__ outS, float* __restrict__ outD, int E) {
    const int AS = 320;
    extern __shared__ uint32_t sm[];
    uint32_t* A = sm;                  // 32*320 words
    uint32_t* Wf = sm + 32 * 320;      // WF_WORDS
    int tid = threadIdx.x, lane = tid & 31, warp = tid >> 5;
    int g = lane >> 2, t4 = lane & 3;
    int e0 = blockIdx.x * 32;
    int ntB = warp * 4;

    // Fill A: srcF/dstF rows (64 float4 per edge)
    for (int i = tid; i < 32 * 64; i += 128) {
        int r = i >> 6, p = i & 63;
        int e = e0 + r;
        bool ok = e < E;
        float4 v = make_float4(0.f, 0.f, 0.f, 0.f);
        int col;
        if (p < 32) {
            col = p * 4;
            if (ok) v = ldg4(&fS[(size_t)e * 128 + p * 4]);
        } else {
            col = 128 + (p - 32) * 4;
            if (ok) v = ldg4(&fD[(size_t)e * 128 + (p - 32) * 4]);
        }
        uint4 u;
        u.x = f2tf(v.x); u.y = f2tf(v.y); u.z = f2tf(v.z); u.w = f2tf(v.w);
        *(uint4*)&A[r * AS + (col ^ ((r & 7) << 2))] = u;
    }
    // te2 cols [256,320)
    for (int i = tid; i < 32 * 16; i += 128) {
        int r = i >> 4, q = (i & 15) * 4;
        int e = e0 + r;
        float t = (e < E) ? __ldg(&ts[e]) : 0.f;
        uint4 u;
        u.x = f2tf(cosf(t * __ldg(&omega[q + 0]) + __ldg(&phase[q + 0])));
        u.y = f2tf(cosf(t * __ldg(&omega[q + 1]) + __ldg(&phase[q + 1])));
        u.z = f2tf(cosf(t * __ldg(&omega[q + 2]) + __ldg(&phase[q + 2])));
        u.w = f2tf(cosf(t * __ldg(&omega[q + 3]) + __ldg(&phase[q + 3])));
        *(uint4*)&A[r * AS + ((256 + q) ^ ((r & 7) << 2))] = u;
    }

    float accS[2][4][4], accD[2][4][4], accH[2][4][4];
#pragma unroll
    for (int m = 0; m < 2; m++)
#pragma unroll
        for (int nt = 0; nt < 4; nt++)
#pragma unroll
            for (int k = 0; k < 4; k++) {
                accS[m][nt][k] = 0.f; accD[m][nt][k] = 0.f; accH[m][nt][k] = 0.f;
            }

    // Head: W rows [0,128); src = A cols k, dst = A cols 128+k
    for (int kc = 0; kc < 128; kc += 16) {
        __syncthreads();
        fillW(&W[(size_t)kc * 128], Wf, tid);
        __syncthreads();
#pragma unroll
        for (int ks2 = 0; ks2 < 2; ks2++) {
            int k0 = kc + ks2 * 8;
            uint32_t aS4[2][4], aD4[2][4];
            ldA(aS4[0], A, AS, 0, k0, g, t4);
            ldA(aS4[1], A, AS, 16, k0, g, t4);
            ldA(aD4[0], A, AS, 0, 128 + k0, g, t4);
            ldA(aD4[1], A, AS, 16, 128 + k0, g, t4);
#pragma unroll
            for (int nt = 0; nt < 4; nt++) {
                uint2 bf = *(const uint2*)&Wf[((ks2 * 16 + ntB + nt) * 32 + lane) * 2];
                mma8(accS[0][nt], aS4[0], (const uint32_t*)&bf);
                mma8(accS[1][nt], aS4[1], (const uint32_t*)&bf);
                mma8(accD[0][nt], aD4[0], (const uint32_t*)&bf);
                mma8(accD[1][nt], aD4[1], (const uint32_t*)&bf);
            }
        }
    }
    // te: W rows [128,192); A cols [256,320)
    for (int kc = 0; kc < 64; kc += 16) {
        __syncthreads();
        fillW(&W[(size_t)(128 + kc) * 128], Wf, tid);
        __syncthreads();
#pragma unroll
        for (int ks2 = 0; ks2 < 2; ks2++) {
            int k0 = 256 + kc + ks2 * 8;
            uint32_t aH4[2][4];
            ldA(aH4[0], A, AS, 0, k0, g, t4);
            ldA(aH4[1], A, AS, 16, k0, g, t4);
#pragma unroll
            for (int nt = 0; nt < 4; nt++) {
                uint2 bf = *(const uint2*)&Wf[((ks2 * 16 + ntB + nt) * 32 + lane) * 2];
                mma8(accH[0][nt], aH4[0], (const uint32_t*)&bf);
                mma8(accH[1][nt], aH4[1], (const uint32_t*)&bf);
            }
        }
    }

#pragma unroll
    for (int m = 0; m < 2; m++)
#pragma unroll
        for (int h = 0; h < 2; h++) {
            int r = m * 16 + h * 8 + g;
            int e = e0 + r;
            if (e < E) {
                int s = __ldg(&src[e]), d = __ldg(&dst[e]);
#pragma unroll
                for (int nt = 0; nt < 4; nt++) {
                    int col = (ntB + nt) * 8 + t4 * 2;
                    float2 bb = __ldg((const float2*)&bias[col]);
                    float2 pS = __ldg((const float2*)&proj[(size_t)s * 128 + col]);
                    float2 pD = __ldg((const float2*)&proj[(size_t)d * 128 + col]);
                    float hx = accH[m][nt][h * 2 + 0], hy = accH[m][nt][h * 2 + 1];
                    float2 os, od;
                    os.x = fmaxf(accS[m][nt][h * 2 + 0] + hx + bb.x + pS.x, 0.f);
                    os.y = fmaxf(accS[m][nt][h * 2 + 1] + hy + bb.y + pS.y, 0.f);
                    od.x = fmaxf(accD[m][nt][h * 2 + 0] + hx + bb.x + pD.x, 0.f);
                    od.y = fmaxf(accD[m][nt][h * 2 + 1] + hy + bb.y + pD.y, 0.f);
                    *(float2*)&outS[(size_t)e * 128 + col] = os;
                    *(float2*)&outD[(size_t)e * 128 + col] = od;
                }
            }
        }
}

// ---------------------------------------------------------------------------
extern "C" void kernel_launch(void* const* d_in, const int* in_sizes, int n_in,
                              void* d_out, int out_size) {
    const float* nfeat = (const float*)d_in[0];
    const float* efeat = (const float*)d_in[1];
    const int*   src   = (const int*)d_in[2];
    const int*   dst   = (const int*)d_in[3];
    const float* ts    = (const float*)d_in[4];
    const float* Ws1 = (const float*)d_in[5];
    const float* bs1 = (const float*)d_in[6];
    const float* Wn1 = (const float*)d_in[7];
    const float* bn1 = (const float*)d_in[8];
    const float* om1 = (const float*)d_in[9];
    const float* ph1 = (const float*)d_in[10];
    const float* Ws2 = (const float*)d_in[11];
    const float* bs2 = (const float*)d_in[12];
    const float* Wn2 = (const float*)d_in[13];
    const float* bn2 = (const float*)d_in[14];
    const float* om2 = (const float*)d_in[15];
    const float* ph2 = (const float*)d_in[16];

    int Nn = in_sizes[0] / 64;
    int E  = in_sizes[2];

    float *cnt, *s1, *s2, *proj, *sf, *df;
    cudaGetSymbolAddress((void**)&cnt,  g_cnt);
    cudaGetSymbolAddress((void**)&s1,   g_sum1);
    cudaGetSymbolAddress((void**)&s2,   g_sum2);
    cudaGetSymbolAddress((void**)&proj, g_proj);
    cudaGetSymbolAddress((void**)&sf,   g_srcF);
    cudaGetSymbolAddress((void**)&df,   g_dstF);

    float* outv = (float*)d_out;
    int nTileBlocks = (Nn + 31) / 32;
    int eTileBlocks = (E + 31) / 32;

    size_t smProj = (size_t)(32 * 128 + WF_WORDS) * 4;   // 24.0 KB
    size_t smL1   = (size_t)(32 * 256 + WF_WORDS) * 4;   // 40.0 KB
    size_t smL2   = (size_t)(32 * 320 + WF_WORDS) * 4;   // 48.0 KB

    cudaFuncSetAttribute(k_proj_t,   cudaFuncAttributeMaxDynamicSharedMemorySize, (int)smProj);
    cudaFuncSetAttribute(k_layer1_t, cudaFuncAttributeMaxDynamicSharedMemorySize, (int)smL1);
    cudaFuncSetAttribute(k_layer2_t, cudaFuncAttributeMaxDynamicSharedMemorySize, (int)smL2);

    k_zero<<<2048, 256>>>(cnt, s1, s2, Nn);
    k_agg1<<<2048, 256>>>(nfeat, efeat, src, dst, s1, cnt, E);
    k_proj_t<<<nTileBlocks, 128, smProj>>>(s1, cnt, Wn1, bn1, proj, Nn);
    k_layer1_t<<<eTileBlocks, 128, smL1>>>(nfeat, efeat, src, dst, ts, Ws1, bs1, om1, ph1,
                                           proj, sf, df, s2, E);
    k_proj_t<<<nTileBlocks, 128, smProj>>>(s2, cnt, Wn2, bn2, proj, Nn);
    k_layer2_t<<<eTileBlocks, 128, smL2>>>(sf, df, src, dst, ts, Ws2, bs2, om2, ph2,
                                           proj, outv, outv + (size_t)E * 128, E);
}

// round 9
// speedup vs baseline: 2.6339x; 2.6339x over previous
#include <cuda_runtime.h>
#include <math.h>
#include <stdint.h>

// Problem sizes (fixed by the dataset)
#define NN 100000
#define EE 500000

// Scratch (device globals; allocation-free per harness rules)
__device__ float g_cnt[NN];
__device__ float g_sum1[(size_t)NN * 128];
__device__ float g_sum2[(size_t)NN * 128];
__device__ float g_proj[(size_t)NN * 128];
__device__ float g_srcF[(size_t)EE * 128];
__device__ float g_dstF[(size_t)EE * 128];

__device__ __forceinline__ float4 ldg4(const float* p) {
    return __ldg((const float4*)p);
}

__device__ __forceinline__ void red4(float* p, float4 v) {
    asm volatile("red.global.add.v4.f32 [%0], {%1,%2,%3,%4};"
                 :: "l"(p), "f"(v.x), "f"(v.y), "f"(v.z), "f"(v.w) : "memory");
}
__device__ __forceinline__ void red2(float* p, float2 v) {
    asm volatile("red.global.add.v2.f32 [%0], {%1,%2};"
                 :: "l"(p), "f"(v.x), "f"(v.y) : "memory");
}

// fp32 -> tf32 (round to nearest)
__device__ __forceinline__ uint32_t f2tf(float f) {
    uint32_t u;
    asm("cvt.rna.tf32.f32 %0, %1;" : "=r"(u) : "f"(f));
    return u;
}

// D += A(16x8) * B(8x8), tf32 inputs, f32 accum
__device__ __forceinline__ void mma8(float* c, const uint32_t* a, const uint32_t* b) {
    asm volatile(
        "mma.sync.aligned.m16n8k8.row.col.f32.tf32.tf32.f32 "
        "{%0,%1,%2,%3}, {%4,%5,%6,%7}, {%8,%9}, {%0,%1,%2,%3};"
        : "+f"(c[0]), "+f"(c[1]), "+f"(c[2]), "+f"(c[3])
        : "r"(a[0]), "r"(a[1]), "r"(a[2]), "r"(a[3]), "r"(b[0]), "r"(b[1]));
}

// Load A fragment (m16 x k8) from swizzled smem tile.
// swizzle: element (r, c) stored at col c ^ ((r&7)<<2). stride % 32 == 0.
// Conflict-free: lanes differ in bits 2-4 (g) and 0-1 (t4) of the column.
__device__ __forceinline__ void ldA(uint32_t a[4], const uint32_t* As, int stride,
                                    int rowBase, int k0, int g, int t4) {
    int key = g << 2;
    const uint32_t* p0 = As + (size_t)(rowBase + g) * stride;
    const uint32_t* p1 = p0 + (size_t)8 * stride;
    int c0 = (k0 + t4) ^ key;
    int c1 = (k0 + 4 + t4) ^ key;
    a[0] = p0[c0];
    a[1] = p1[c0];
    a[2] = p0[c1];
    a[3] = p1[c1];
}

// Load B fragment (k8 x n8) straight from row-major W in gmem (L2-resident).
// b0 = W[k0+t4][col+g], b1 = W[k0+t4+4][col+g]
__device__ __forceinline__ void ldB(uint32_t b[2], const float* __restrict__ Wrow,
                                    int nt8) {
    b[0] = f2tf(__ldg(&Wrow[nt8]));
    b[1] = f2tf(__ldg(&Wrow[nt8 + 4 * 128]));
}

// ---------------------------------------------------------------------------
// Zero cnt + sum1 + sum2
// ---------------------------------------------------------------------------
__global__ void k_zero(float* cnt, float* s1, float* s2, int n) {
    int i = blockIdx.x * blockDim.x + threadIdx.x;
    int stride = gridDim.x * blockDim.x;
    int t4 = n * 32;
    float4 z = make_float4(0.f, 0.f, 0.f, 0.f);
    for (int j = i; j < t4; j += stride) {
        ((float4*)s1)[j] = z;
        ((float4*)s2)[j] = z;
    }
    for (int j = i; j < n; j += stride) cnt[j] = 0.f;
}

// ---------------------------------------------------------------------------
// Layer-1 aggregation (L2 atomics)
// ---------------------------------------------------------------------------
__global__ void k_agg1(const float* __restrict__ nfeat, const float* __restrict__ efeat,
                       const int* __restrict__ src, const int* __restrict__ dst,
                       float* sum1, float* cnt, int E) {
    int warp = (blockIdx.x * blockDim.x + threadIdx.x) >> 5;
    int lane = threadIdx.x & 31;
    int nw = (gridDim.x * blockDim.x) >> 5;
    for (int e = warp; e < E; e += nw) {
        int s = __ldg(&src[e]);
        int d = __ldg(&dst[e]);
        float4 vs, vd;
        int off;
        if (lane < 16) {
            off = lane * 4;
            vs = ldg4(&nfeat[(size_t)d * 64 + off]);
            vd = ldg4(&nfeat[(size_t)s * 64 + off]);
        } else {
            int q = (lane - 16) * 4;
            off = 64 + q;
            float4 ef = ldg4(&efeat[(size_t)e * 64 + q]);
            vs = ef; vd = ef;
        }
        red4(&sum1[(size_t)s * 128 + off], vs);
        red4(&sum1[(size_t)d * 128 + off], vd);
        if (lane == 0) {
            atomicAdd(&cnt[s], 1.f);
            atomicAdd(&cnt[d], 1.f);
        }
    }
}

// ---------------------------------------------------------------------------
// Tensor-core node projection: proj[n] = (sum[n]/max(cnt,1)) @ W[128,128] + b
// Block: 128 threads / 4 warps / 32 nodes. Warp tile 32x32. B direct from gmem.
// ---------------------------------------------------------------------------
__global__ __launch_bounds__(128, 3) void k_proj_t(
    const float* __restrict__ sum, const float* __restrict__ cnt,
    const float* __restrict__ W, const float* __restrict__ bias,
    float* __restrict__ proj, int Nn) {
    extern __shared__ uint32_t sm[];
    uint32_t* As = sm;                 // 32*128 words
    __shared__ float invS[32];
    int tid = threadIdx.x, lane = tid & 31, warp = tid >> 5;
    int g = lane >> 2, t4 = lane & 3;
    int n0 = blockIdx.x * 32;
    int ntB = warp * 4;

    if (tid < 32) {
        int n = n0 + tid;
        float c = 1.f;
        if (n < Nn) c = fmaxf(__ldg(&cnt[n]), 1.f);
        invS[tid] = 1.f / c;
    }
    __syncthreads();
    for (int i = tid; i < 32 * 32; i += 128) {
        int r = i >> 5, q = (i & 31) * 4;
        int n = n0 + r;
        float4 v = make_float4(0.f, 0.f, 0.f, 0.f);
        if (n < Nn) v = ldg4(&sum[(size_t)n * 128 + q]);
        float s = invS[r];
        uint4 u;
        u.x = f2tf(v.x * s); u.y = f2tf(v.y * s);
        u.z = f2tf(v.z * s); u.w = f2tf(v.w * s);
        *(uint4*)&As[r * 128 + (q ^ ((r & 7) << 2))] = u;
    }
    __syncthreads();

    float acc[2][4][4];
#pragma unroll
    for (int m = 0; m < 2; m++)
#pragma unroll
        for (int nt = 0; nt < 4; nt++)
#pragma unroll
            for (int k = 0; k < 4; k++) acc[m][nt][k] = 0.f;

    for (int ks = 0; ks < 16; ks++) {
        int k0 = ks * 8;
        uint32_t a[2][4];
        ldA(a[0], As, 128, 0, k0, g, t4);
        ldA(a[1], As, 128, 16, k0, g, t4);
        const float* Wrow = &W[(size_t)(k0 + t4) * 128 + ntB * 8 + g];
#pragma unroll
        for (int nt = 0; nt < 4; nt++) {
            uint32_t bf[2];
            ldB(bf, Wrow, nt * 8);
            mma8(acc[0][nt], a[0], bf);
            mma8(acc[1][nt], a[1], bf);
        }
    }

#pragma unroll
    for (int m = 0; m < 2; m++)
#pragma unroll
        for (int h = 0; h < 2; h++) {
            int r = m * 16 + h * 8 + g;
            int n = n0 + r;
            if (n < Nn) {
#pragma unroll
                for (int nt = 0; nt < 4; nt++) {
                    int col = (ntB + nt) * 8 + t4 * 2;
                    float2 bb = __ldg((const float2*)&bias[col]);
                    float2 o;
                    o.x = acc[m][nt][h * 2 + 0] + bb.x;
                    o.y = acc[m][nt][h * 2 + 1] + bb.y;
                    *(float2*)&proj[(size_t)n * 128 + col] = o;
                }
            }
        }
}

// ---------------------------------------------------------------------------
// Tensor-core layer-1 edge kernel. Block: 128 thr / 4 warps / 32 edges.
// A (tf32, swizzled, stride 256): [0,64)=nfeat[src], [64,128)=nfeat[dst],
//                                 [128,192)=efeat, [192,256)=te
// W rows: [0,64) head (per src/dst), [64,192) shared. B direct from gmem.
// ---------------------------------------------------------------------------
__global__ __launch_bounds__(128, 3) void k_layer1_t(
    const float* __restrict__ nfeat, const float* __restrict__ efeat,
    const int* __restrict__ src, const int* __restrict__ dst, const float* __restrict__ ts,
    const float* __restrict__ W, const float* __restrict__ bias,
    const float* __restrict__ omega, const float* __restrict__ phase,
    const float* __restrict__ proj, float* __restrict__ outS, float* __restrict__ outD,
    float* __restrict__ sum2, int E) {
    const int AS = 256;
    extern __shared__ uint32_t sm[];
    uint32_t* A = sm;                  // 32*256 words
    __shared__ int sI[32], dI[32];
    __shared__ float tsS[32];
    int tid = threadIdx.x, lane = tid & 31, warp = tid >> 5;
    int g = lane >> 2, t4 = lane & 3;
    int e0 = blockIdx.x * 32;
    int ntB = warp * 4;

    if (tid < 32) {
        int e = e0 + tid;
        bool ok = e < E;
        sI[tid] = ok ? __ldg(&src[e]) : 0;
        dI[tid] = ok ? __ldg(&dst[e]) : 0;
        tsS[tid] = ok ? __ldg(&ts[e]) : 0.f;
    }
    __syncthreads();

    // Fill A (48 float4 per edge), converted to tf32, swizzled.
    for (int i = tid; i < 32 * 48; i += 128) {
        int r = i / 48, p = i % 48;
        int e = e0 + r;
        bool ok = e < E;
        float4 v = make_float4(0.f, 0.f, 0.f, 0.f);
        int col;
        if (p < 16) {
            col = p * 4;
            if (ok) v = ldg4(&nfeat[(size_t)sI[r] * 64 + p * 4]);
        } else if (p < 32) {
            col = 64 + (p - 16) * 4;
            if (ok) v = ldg4(&nfeat[(size_t)dI[r] * 64 + (p - 16) * 4]);
        } else {
            col = 128 + (p - 32) * 4;
            if (ok) v = ldg4(&efeat[(size_t)e * 64 + (p - 32) * 4]);
        }
        uint4 u;
        u.x = f2tf(v.x); u.y = f2tf(v.y); u.z = f2tf(v.z); u.w = f2tf(v.w);
        *(uint4*)&A[r * AS + (col ^ ((r & 7) << 2))] = u;
    }
    // te cols [192,256)
    for (int i = tid; i < 32 * 16; i += 128) {
        int r = i >> 4, q = (i & 15) * 4;
        float t = tsS[r];
        uint4 u;
        u.x = f2tf(cosf(t * __ldg(&omega[q + 0]) + __ldg(&phase[q + 0])));
        u.y = f2tf(cosf(t * __ldg(&omega[q + 1]) + __ldg(&phase[q + 1])));
        u.z = f2tf(cosf(t * __ldg(&omega[q + 2]) + __ldg(&phase[q + 2])));
        u.w = f2tf(cosf(t * __ldg(&omega[q + 3]) + __ldg(&phase[q + 3])));
        *(uint4*)&A[r * AS + ((192 + q) ^ ((r & 7) << 2))] = u;
    }
    __syncthreads();

    float accS[2][4][4], accD[2][4][4], accH[2][4][4];
#pragma unroll
    for (int m = 0; m < 2; m++)
#pragma unroll
        for (int nt = 0; nt < 4; nt++)
#pragma unroll
            for (int k = 0; k < 4; k++) {
                accS[m][nt][k] = 0.f; accD[m][nt][k] = 0.f; accH[m][nt][k] = 0.f;
            }

    // Head: W rows [0,64); src = A cols k0, dst = A cols 64+k0
    for (int ks = 0; ks < 8; ks++) {
        int k0 = ks * 8;
        uint32_t aS4[2][4], aD4[2][4];
        ldA(aS4[0], A, AS, 0, k0, g, t4);
        ldA(aS4[1], A, AS, 16, k0, g, t4);
        ldA(aD4[0], A, AS, 0, 64 + k0, g, t4);
        ldA(aD4[1], A, AS, 16, 64 + k0, g, t4);
        const float* Wrow = &W[(size_t)(k0 + t4) * 128 + ntB * 8 + g];
#pragma unroll
        for (int nt = 0; nt < 4; nt++) {
            uint32_t bf[2];
            ldB(bf, Wrow, nt * 8);
            mma8(accS[0][nt], aS4[0], bf);
            mma8(accS[1][nt], aS4[1], bf);
            mma8(accD[0][nt], aD4[0], bf);
            mma8(accD[1][nt], aD4[1], bf);
        }
    }
    // Shared: W rows [64,192); A cols [128,256)
    for (int ks = 0; ks < 16; ks++) {
        int k0 = ks * 8;
        uint32_t aH4[2][4];
        ldA(aH4[0], A, AS, 0, 128 + k0, g, t4);
        ldA(aH4[1], A, AS, 16, 128 + k0, g, t4);
        const float* Wrow = &W[(size_t)(64 + k0 + t4) * 128 + ntB * 8 + g];
#pragma unroll
        for (int nt = 0; nt < 4; nt++) {
            uint32_t bf[2];
            ldB(bf, Wrow, nt * 8);
            mma8(accH[0][nt], aH4[0], bf);
            mma8(accH[1][nt], aH4[1], bf);
        }
    }

    // Epilogue: bias + proj gather + relu; scratch write; fused layer-2 segment-sum
#pragma unroll
    for (int m = 0; m < 2; m++)
#pragma unroll
        for (int h = 0; h < 2; h++) {
            int r = m * 16 + h * 8 + g;
            int e = e0 + r;
            if (e < E) {
                int s = sI[r], d = dI[r];
#pragma unroll
                for (int nt = 0; nt < 4; nt++) {
                    int col = (ntB + nt) * 8 + t4 * 2;
                    float2 bb = __ldg((const float2*)&bias[col]);
                    float2 pS = __ldg((const float2*)&proj[(size_t)s * 128 + col]);
                    float2 pD = __ldg((const float2*)&proj[(size_t)d * 128 + col]);
                    float hx = accH[m][nt][h * 2 + 0], hy = accH[m][nt][h * 2 + 1];
                    float2 os, od;
                    os.x = fmaxf(accS[m][nt][h * 2 + 0] + hx + bb.x + pS.x, 0.f);
                    os.y = fmaxf(accS[m][nt][h * 2 + 1] + hy + bb.y + pS.y, 0.f);
                    od.x = fmaxf(accD[m][nt][h * 2 + 0] + hx + bb.x + pD.x, 0.f);
                    od.y = fmaxf(accD[m][nt][h * 2 + 1] + hy + bb.y + pD.y, 0.f);
                    *(float2*)&outS[(size_t)e * 128 + col] = os;
                    *(float2*)&outD[(size_t)e * 128 + col] = od;
                    red2(&sum2[(size_t)s * 128 + col], od);
                    red2(&sum2[(size_t)d * 128 + col], os);
                }
            }
        }
}

// ---------------------------------------------------------------------------
// Tensor-core layer-2 edge kernel. Block: 128 thr / 4 warps / 32 edges.
// A (tf32, swizzled, stride 320): [0,128)=srcF, [128,256)=dstF, [256,320)=te2
// W rows: [0,128) head, [128,192) te (shared). Writes final output.
// ---------------------------------------------------------------------------
__global__ __launch_bounds__(128, 3) void k_layer2_t(
    const float* __restrict__ fS, const float* __restrict__ fD,
    const int* __restrict__ src, const int* __restrict__ dst, const float* __restrict__ ts,
    const float* __restrict__ W, const float* __restrict__ bias,
    const float* __restrict__ omega, const float* __restrict__ phase,
    const float* __restrict__ proj, float* __restrict__ outS, float* __restrict__ outD, int E) {
    const int AS = 320;
    extern __shared__ uint32_t sm[];
    uint32_t* A = sm;                  // 32*320 words
    int tid = threadIdx.x, lane = tid & 31, warp = tid >> 5;
    int g = lane >> 2, t4 = lane & 3;
    int e0 = blockIdx.x * 32;
    int ntB = warp * 4;

    // Fill A: srcF/dstF rows (64 float4 per edge)
    for (int i = tid; i < 32 * 64; i += 128) {
        int r = i >> 6, p = i & 63;
        int e = e0 + r;
        bool ok = e < E;
        float4 v = make_float4(0.f, 0.f, 0.f, 0.f);
        int col;
        if (p < 32) {
            col = p * 4;
            if (ok) v = ldg4(&fS[(size_t)e * 128 + p * 4]);
        } else {
            col = 128 + (p - 32) * 4;
            if (ok) v = ldg4(&fD[(size_t)e * 128 + (p - 32) * 4]);
        }
        uint4 u;
        u.x = f2tf(v.x); u.y = f2tf(v.y); u.z = f2tf(v.z); u.w = f2tf(v.w);
        *(uint4*)&A[r * AS + (col ^ ((r & 7) << 2))] = u;
    }
    // te2 cols [256,320)
    for (int i = tid; i < 32 * 16; i += 128) {
        int r = i >> 4, q = (i & 15) * 4;
        int e = e0 + r;
        float t = (e < E) ? __ldg(&ts[e]) : 0.f;
        uint4 u;
        u.x = f2tf(cosf(t * __ldg(&omega[q + 0]) + __ldg(&phase[q + 0])));
        u.y = f2tf(cosf(t * __ldg(&omega[q + 1]) + __ldg(&phase[q + 1])));
        u.z = f2tf(cosf(t * __ldg(&omega[q + 2]) + __ldg(&phase[q + 2])));
        u.w = f2tf(cosf(t * __ldg(&omega[q + 3]) + __ldg(&phase[q + 3])));
        *(uint4*)&A[r * AS + ((256 + q) ^ ((r & 7) << 2))] = u;
    }
    __syncthreads();

    float accS[2][4][4], accD[2][4][4], accH[2][4][4];
#pragma unroll
    for (int m = 0; m < 2; m++)
#pragma unroll
        for (int nt = 0; nt < 4; nt++)
#pragma unroll
            for (int k = 0; k < 4; k++) {
                accS[m][nt][k] = 0.f; accD[m][nt][k] = 0.f; accH[m][nt][k] = 0.f;
            }

    // Head: W rows [0,128); src = A cols k0, dst = A cols 128+k0
    for (int ks = 0; ks < 16; ks++) {
        int k0 = ks * 8;
        uint32_t aS4[2][4], aD4[2][4];
        ldA(aS4[0], A, AS, 0, k0, g, t4);
        ldA(aS4[1], A, AS, 16, k0, g, t4);
        ldA(aD4[0], A, AS, 0, 128 + k0, g, t4);
        ldA(aD4[1], A, AS, 16, 128 + k0, g, t4);
        const float* Wrow = &W[(size_t)(k0 + t4) * 128 + ntB * 8 + g];
#pragma unroll
        for (int nt = 0; nt < 4; nt++) {
            uint32_t bf[2];
            ldB(bf, Wrow, nt * 8);
            mma8(accS[0][nt], aS4[0], bf);
            mma8(accS[1][nt], aS4[1], bf);
            mma8(accD[0][nt], aD4[0], bf);
            mma8(accD[1][nt], aD4[1], bf);
        }
    }
    // te: W rows [128,192); A cols [256,320)
    for (int ks = 0; ks < 8; ks++) {
        int k0 = ks * 8;
        uint32_t aH4[2][4];
        ldA(aH4[0], A, AS, 0, 256 + k0, g, t4);
        ldA(aH4[1], A, AS, 16, 256 + k0, g, t4);
        const float* Wrow = &W[(size_t)(128 + k0 + t4) * 128 + ntB * 8 + g];
#pragma unroll
        for (int nt = 0; nt < 4; nt++) {
            uint32_t bf[2];
            ldB(bf, Wrow, nt * 8);
            mma8(accH[0][nt], aH4[0], bf);
            mma8(accH[1][nt], aH4[1], bf);
        }
    }

#pragma unroll
    for (int m = 0; m < 2; m++)
#pragma unroll
        for (int h = 0; h < 2; h++) {
            int r = m * 16 + h * 8 + g;
            int e = e0 + r;
            if (e < E) {
                int s = __ldg(&src[e]), d = __ldg(&dst[e]);
#pragma unroll
                for (int nt = 0; nt < 4; nt++) {
                    int col = (ntB + nt) * 8 + t4 * 2;
                    float2 bb = __ldg((const float2*)&bias[col]);
                    float2 pS = __ldg((const float2*)&proj[(size_t)s * 128 + col]);
                    float2 pD = __ldg((const float2*)&proj[(size_t)d * 128 + col]);
                    float hx = accH[m][nt][h * 2 + 0], hy = accH[m][nt][h * 2 + 1];
                    float2 os, od;
                    os.x = fmaxf(accS[m][nt][h * 2 + 0] + hx + bb.x + pS.x, 0.f);
                    os.y = fmaxf(accS[m][nt][h * 2 + 1] + hy + bb.y + pS.y, 0.f);
                    od.x = fmaxf(accD[m][nt][h * 2 + 0] + hx + bb.x + pD.x, 0.f);
                    od.y = fmaxf(accD[m][nt][h * 2 + 1] + hy + bb.y + pD.y, 0.f);
                    *(float2*)&outS[(size_t)e * 128 + col] = os;
                    *(float2*)&outD[(size_t)e * 128 + col] = od;
                }
            }
        }
}

// ---------------------------------------------------------------------------
extern "C" void kernel_launch(void* const* d_in, const int* in_sizes, int n_in,
                              void* d_out, int out_size) {
    const float* nfeat = (const float*)d_in[0];
    const float* efeat = (const float*)d_in[1];
    const int*   src   = (const int*)d_in[2];
    const int*   dst   = (const int*)d_in[3];
    const float* ts    = (const float*)d_in[4];
    const float* Ws1 = (const float*)d_in[5];
    const float* bs1 = (const float*)d_in[6];
    const float* Wn1 = (const float*)d_in[7];
    const float* bn1 = (const float*)d_in[8];
    const float* om1 = (const float*)d_in[9];
    const float* ph1 = (const float*)d_in[10];
    const float* Ws2 = (const float*)d_in[11];
    const float* bs2 = (const float*)d_in[12];
    const float* Wn2 = (const float*)d_in[13];
    const float* bn2 = (const float*)d_in[14];
    const float* om2 = (const float*)d_in[15];
    const float* ph2 = (const float*)d_in[16];

    int Nn = in_sizes[0] / 64;
    int E  = in_sizes[2];

    float *cnt, *s1, *s2, *proj, *sf, *df;
    cudaGetSymbolAddress((void**)&cnt,  g_cnt);
    cudaGetSymbolAddress((void**)&s1,   g_sum1);
    cudaGetSymbolAddress((void**)&s2,   g_sum2);
    cudaGetSymbolAddress((void**)&proj, g_proj);
    cudaGetSymbolAddress((void**)&sf,   g_srcF);
    cudaGetSymbolAddress((void**)&df,   g_dstF);

    float* outv = (float*)d_out;
    int nTileBlocks = (Nn + 31) / 32;
    int eTileBlocks = (E + 31) / 32;

    size_t smProj = (size_t)(32 * 128) * 4;   // 16 KB
    size_t smL1   = (size_t)(32 * 256) * 4;   // 32 KB
    size_t smL2   = (size_t)(32 * 320) * 4;   // 40 KB

    cudaFuncSetAttribute(k_proj_t,   cudaFuncAttributeMaxDynamicSharedMemorySize, (int)smProj);
    cudaFuncSetAttribute(k_layer1_t, cudaFuncAttributeMaxDynamicSharedMemorySize, (int)smL1);
    cudaFuncSetAttribute(k_layer2_t, cudaFuncAttributeMaxDynamicSharedMemorySize, (int)smL2);

    k_zero<<<2048, 256>>>(cnt, s1, s2, Nn);
    k_agg1<<<2048, 256>>>(nfeat, efeat, src, dst, s1, cnt, E);
    k_proj_t<<<nTileBlocks, 128, smProj>>>(s1, cnt, Wn1, bn1, proj, Nn);
    k_layer1_t<<<eTileBlocks, 128, smL1>>>(nfeat, efeat, src, dst, ts, Ws1, bs1, om1, ph1,
                                           proj, sf, df, s2, E);
    k_proj_t<<<nTileBlocks, 128, smProj>>>(s2, cnt, Wn2, bn2, proj, Nn);
    k_layer2_t<<<eTileBlocks, 128, smL2>>>(sf, df, src, dst, ts, Ws2, bs2, om2, ph2,
                                           proj, outv, outv + (size_t)E * 128, E);
}

// round 10
// speedup vs baseline: 2.6588x; 1.0095x over previous
#include <cuda_runtime.h>
#include <math.h>
#include <stdint.h>

// Problem sizes (fixed by the dataset)
#define NN 100000
#define EE 500000

// Scratch (device globals; allocation-free per harness rules)
__device__ float g_cnt[NN];
__device__ float g_sum1[(size_t)NN * 128];
__device__ float g_sum2[(size_t)NN * 128];
__device__ float g_proj[(size_t)NN * 128];
__device__ float g_srcF[(size_t)EE * 128];
__device__ float g_dstF[(size_t)EE * 128];

__device__ __forceinline__ float4 ldg4(const float* p) {
    return __ldg((const float4*)p);
}

__device__ __forceinline__ void red4(float* p, float4 v) {
    asm volatile("red.global.add.v4.f32 [%0], {%1,%2,%3,%4};"
                 :: "l"(p), "f"(v.x), "f"(v.y), "f"(v.z), "f"(v.w) : "memory");
}

// fp32 -> tf32 (round to nearest)
__device__ __forceinline__ uint32_t f2tf(float f) {
    uint32_t u;
    asm("cvt.rna.tf32.f32 %0, %1;" : "=r"(u) : "f"(f));
    return u;
}

// D += A(16x8) * B(8x8), tf32 inputs, f32 accum
__device__ __forceinline__ void mma8(float* c, const uint32_t* a, const uint32_t* b) {
    asm volatile(
        "mma.sync.aligned.m16n8k8.row.col.f32.tf32.tf32.f32 "
        "{%0,%1,%2,%3}, {%4,%5,%6,%7}, {%8,%9}, {%0,%1,%2,%3};"
        : "+f"(c[0]), "+f"(c[1]), "+f"(c[2]), "+f"(c[3])
        : "r"(a[0]), "r"(a[1]), "r"(a[2]), "r"(a[3]), "r"(b[0]), "r"(b[1]));
}

// Load A fragment (m16 x k8) from swizzled smem tile.
// swizzle: element (r, c) stored at col c ^ ((r&7)<<2). stride % 32 == 0.
__device__ __forceinline__ void ldA(uint32_t a[4], const uint32_t* As, int stride,
                                    int rowBase, int k0, int g, int t4) {
    int key = g << 2;
    const uint32_t* p0 = As + (size_t)(rowBase + g) * stride;
    const uint32_t* p1 = p0 + (size_t)8 * stride;
    int c0 = (k0 + t4) ^ key;
    int c1 = (k0 + 4 + t4) ^ key;
    a[0] = p0[c0];
    a[1] = p1[c0];
    a[2] = p0[c1];
    a[3] = p1[c1];
}

// Load B fragment (k8 x n8) straight from row-major W in gmem (L2/L1-resident).
__device__ __forceinline__ void ldB(uint32_t b[2], const float* __restrict__ Wrow,
                                    int nt8) {
    b[0] = f2tf(__ldg(&Wrow[nt8]));
    b[1] = f2tf(__ldg(&Wrow[nt8 + 4 * 128]));
}

// ---------------------------------------------------------------------------
// Zero cnt + sum1 + sum2
// ---------------------------------------------------------------------------
__global__ void k_zero(float* cnt, float* s1, float* s2, int n) {
    int i = blockIdx.x * blockDim.x + threadIdx.x;
    int stride = gridDim.x * blockDim.x;
    int t4 = n * 32;
    float4 z = make_float4(0.f, 0.f, 0.f, 0.f);
    for (int j = i; j < t4; j += stride) {
        ((float4*)s1)[j] = z;
        ((float4*)s2)[j] = z;
    }
    for (int j = i; j < n; j += stride) cnt[j] = 0.f;
}

// ---------------------------------------------------------------------------
// Layer-1 aggregation (L2 atomics)
// ---------------------------------------------------------------------------
__global__ void k_agg1(const float* __restrict__ nfeat, const float* __restrict__ efeat,
                       const int* __restrict__ src, const int* __restrict__ dst,
                       float* sum1, float* cnt, int E) {
    int warp = (blockIdx.x * blockDim.x + threadIdx.x) >> 5;
    int lane = threadIdx.x & 31;
    int nw = (gridDim.x * blockDim.x) >> 5;
    for (int e = warp; e < E; e += nw) {
        int s = __ldg(&src[e]);
        int d = __ldg(&dst[e]);
        float4 vs, vd;
        int off;
        if (lane < 16) {
            off = lane * 4;
            vs = ldg4(&nfeat[(size_t)d * 64 + off]);
            vd = ldg4(&nfeat[(size_t)s * 64 + off]);
        } else {
            int q = (lane - 16) * 4;
            off = 64 + q;
            float4 ef = ldg4(&efeat[(size_t)e * 64 + q]);
            vs = ef; vd = ef;
        }
        red4(&sum1[(size_t)s * 128 + off], vs);
        red4(&sum1[(size_t)d * 128 + off], vd);
        if (lane == 0) {
            atomicAdd(&cnt[s], 1.f);
            atomicAdd(&cnt[d], 1.f);
        }
    }
}

// ---------------------------------------------------------------------------
// Tensor-core node projection: proj[n] = (sum[n]/max(cnt,1)) @ W[128,128] + b
// Coalesced epilogue via smem staging.
// ---------------------------------------------------------------------------
__global__ __launch_bounds__(128, 3) void k_proj_t(
    const float* __restrict__ sum, const float* __restrict__ cnt,
    const float* __restrict__ W, const float* __restrict__ bias,
    float* __restrict__ proj, int Nn) {
    extern __shared__ uint32_t sm[];
    uint32_t* As = sm;                 // 32*128 words (reused as output staging)
    __shared__ float invS[32];
    int tid = threadIdx.x, lane = tid & 31, warp = tid >> 5;
    int g = lane >> 2, t4 = lane & 3;
    int n0 = blockIdx.x * 32;
    int ntB = warp * 4;

    if (tid < 32) {
        int n = n0 + tid;
        float c = 1.f;
        if (n < Nn) c = fmaxf(__ldg(&cnt[n]), 1.f);
        invS[tid] = 1.f / c;
    }
    __syncthreads();
    for (int i = tid; i < 32 * 32; i += 128) {
        int r = i >> 5, q = (i & 31) * 4;
        int n = n0 + r;
        float4 v = make_float4(0.f, 0.f, 0.f, 0.f);
        if (n < Nn) v = ldg4(&sum[(size_t)n * 128 + q]);
        float s = invS[r];
        uint4 u;
        u.x = f2tf(v.x * s); u.y = f2tf(v.y * s);
        u.z = f2tf(v.z * s); u.w = f2tf(v.w * s);
        *(uint4*)&As[r * 128 + (q ^ ((r & 7) << 2))] = u;
    }
    __syncthreads();

    float acc[2][4][4];
#pragma unroll
    for (int m = 0; m < 2; m++)
#pragma unroll
        for (int nt = 0; nt < 4; nt++)
#pragma unroll
            for (int k = 0; k < 4; k++) acc[m][nt][k] = 0.f;

    for (int ks = 0; ks < 16; ks++) {
        int k0 = ks * 8;
        uint32_t a[2][4];
        ldA(a[0], As, 128, 0, k0, g, t4);
        ldA(a[1], As, 128, 16, k0, g, t4);
        const float* Wrow = &W[(size_t)(k0 + t4) * 128 + ntB * 8 + g];
#pragma unroll
        for (int nt = 0; nt < 4; nt++) {
            uint32_t bf[2];
            ldB(bf, Wrow, nt * 8);
            mma8(acc[0][nt], a[0], bf);
            mma8(acc[1][nt], a[1], bf);
        }
    }

    // Stage accumulators into smem (swizzled), then coalesced writeback
    __syncthreads();
    float* S = (float*)As;   // 32 x 128 floats = 16 KB
#pragma unroll
    for (int m = 0; m < 2; m++)
#pragma unroll
        for (int h = 0; h < 2; h++) {
            int r = m * 16 + h * 8 + g;
            int key = (r & 7) << 2;
#pragma unroll
            for (int nt = 0; nt < 4; nt++) {
                int col = (ntB + nt) * 8 + t4 * 2;
                float2 v = make_float2(acc[m][nt][h * 2 + 0], acc[m][nt][h * 2 + 1]);
                *(float2*)&S[r * 128 + (col ^ key)] = v;
            }
        }
    __syncthreads();
    for (int i = tid; i < 32 * 32; i += 128) {
        int r = i >> 5, q = (i & 31) * 4;
        int n = n0 + r;
        if (n < Nn) {
            int key = (r & 7) << 2;
            float4 v = *(float4*)&S[r * 128 + (q ^ key)];
            float4 bb = ldg4(&bias[q]);
            float4 o;
            o.x = v.x + bb.x; o.y = v.y + bb.y; o.z = v.z + bb.z; o.w = v.w + bb.w;
            *(float4*)&proj[(size_t)n * 128 + q] = o;
        }
    }
}

// ---------------------------------------------------------------------------
// Tensor-core layer-1 edge kernel. Coalesced staged epilogue + fused sum2.
// A (tf32, swizzled, stride 256): [0,64)=nfeat[src], [64,128)=nfeat[dst],
//                                 [128,192)=efeat, [192,256)=te
// W rows: [0,64) head (per src/dst), [64,192) shared. B direct from gmem.
// ---------------------------------------------------------------------------
__global__ __launch_bounds__(128, 3) void k_layer1_t(
    const float* __restrict__ nfeat, const float* __restrict__ efeat,
    const int* __restrict__ src, const int* __restrict__ dst, const float* __restrict__ ts,
    const float* __restrict__ W, const float* __restrict__ bias,
    const float* __restrict__ omega, const float* __restrict__ phase,
    const float* __restrict__ proj, float* __restrict__ outS, float* __restrict__ outD,
    float* __restrict__ sum2, int E) {
    const int AS = 256;
    extern __shared__ uint32_t sm[];
    uint32_t* A = sm;                  // 32*256 words; reused as 2x(32x128) staging
    __shared__ int sI[32], dI[32];
    __shared__ float tsS[32];
    int tid = threadIdx.x, lane = tid & 31, warp = tid >> 5;
    int g = lane >> 2, t4 = lane & 3;
    int e0 = blockIdx.x * 32;
    int ntB = warp * 4;

    if (tid < 32) {
        int e = e0 + tid;
        bool ok = e < E;
        sI[tid] = ok ? __ldg(&src[e]) : 0;
        dI[tid] = ok ? __ldg(&dst[e]) : 0;
        tsS[tid] = ok ? __ldg(&ts[e]) : 0.f;
    }
    __syncthreads();

    // Fill A (48 float4 per edge), converted to tf32, swizzled.
    for (int i = tid; i < 32 * 48; i += 128) {
        int r = i / 48, p = i % 48;
        int e = e0 + r;
        bool ok = e < E;
        float4 v = make_float4(0.f, 0.f, 0.f, 0.f);
        int col;
        if (p < 16) {
            col = p * 4;
            if (ok) v = ldg4(&nfeat[(size_t)sI[r] * 64 + p * 4]);
        } else if (p < 32) {
            col = 64 + (p - 16) * 4;
            if (ok) v = ldg4(&nfeat[(size_t)dI[r] * 64 + (p - 16) * 4]);
        } else {
            col = 128 + (p - 32) * 4;
            if (ok) v = ldg4(&efeat[(size_t)e * 64 + (p - 32) * 4]);
        }
        uint4 u;
        u.x = f2tf(v.x); u.y = f2tf(v.y); u.z = f2tf(v.z); u.w = f2tf(v.w);
        *(uint4*)&A[r * AS + (col ^ ((r & 7) << 2))] = u;
    }
    // te cols [192,256)
    for (int i = tid; i < 32 * 16; i += 128) {
        int r = i >> 4, q = (i & 15) * 4;
        float t = tsS[r];
        uint4 u;
        u.x = f2tf(cosf(t * __ldg(&omega[q + 0]) + __ldg(&phase[q + 0])));
        u.y = f2tf(cosf(t * __ldg(&omega[q + 1]) + __ldg(&phase[q + 1])));
        u.z = f2tf(cosf(t * __ldg(&omega[q + 2]) + __ldg(&phase[q + 2])));
        u.w = f2tf(cosf(t * __ldg(&omega[q + 3]) + __ldg(&phase[q + 3])));
        *(uint4*)&A[r * AS + ((192 + q) ^ ((r & 7) << 2))] = u;
    }
    __syncthreads();

    float accS[2][4][4], accD[2][4][4], accH[2][4][4];
#pragma unroll
    for (int m = 0; m < 2; m++)
#pragma unroll
        for (int nt = 0; nt < 4; nt++)
#pragma unroll
            for (int k = 0; k < 4; k++) {
                accS[m][nt][k] = 0.f; accD[m][nt][k] = 0.f; accH[m][nt][k] = 0.f;
            }

    // Head: W rows [0,64); src = A cols k0, dst = A cols 64+k0
    for (int ks = 0; ks < 8; ks++) {
        int k0 = ks * 8;
        uint32_t aS4[2][4], aD4[2][4];
        ldA(aS4[0], A, AS, 0, k0, g, t4);
        ldA(aS4[1], A, AS, 16, k0, g, t4);
        ldA(aD4[0], A, AS, 0, 64 + k0, g, t4);
        ldA(aD4[1], A, AS, 16, 64 + k0, g, t4);
        const float* Wrow = &W[(size_t)(k0 + t4) * 128 + ntB * 8 + g];
#pragma unroll
        for (int nt = 0; nt < 4; nt++) {
            uint32_t bf[2];
            ldB(bf, Wrow, nt * 8);
            mma8(accS[0][nt], aS4[0], bf);
            mma8(accS[1][nt], aS4[1], bf);
            mma8(accD[0][nt], aD4[0], bf);
            mma8(accD[1][nt], aD4[1], bf);
        }
    }
    // Shared: W rows [64,192); A cols [128,256)
    for (int ks = 0; ks < 16; ks++) {
        int k0 = ks * 8;
        uint32_t aH4[2][4];
        ldA(aH4[0], A, AS, 0, 128 + k0, g, t4);
        ldA(aH4[1], A, AS, 16, 128 + k0, g, t4);
        const float* Wrow = &W[(size_t)(64 + k0 + t4) * 128 + ntB * 8 + g];
#pragma unroll
        for (int nt = 0; nt < 4; nt++) {
            uint32_t bf[2];
            ldB(bf, Wrow, nt * 8);
            mma8(accH[0][nt], aH4[0], bf);
            mma8(accH[1][nt], aH4[1], bf);
        }
    }

    // Stage accS+accH / accD+accH into smem (A is dead), then coalesced writeback
    __syncthreads();
    float* Ss = (float*)A;              // 32x128
    float* Sd = (float*)A + 32 * 128;   // 32x128
#pragma unroll
    for (int m = 0; m < 2; m++)
#pragma unroll
        for (int h = 0; h < 2; h++) {
            int r = m * 16 + h * 8 + g;
            int key = (r & 7) << 2;
#pragma unroll
            for (int nt = 0; nt < 4; nt++) {
                int col = (ntB + nt) * 8 + t4 * 2;
                float hx = accH[m][nt][h * 2 + 0], hy = accH[m][nt][h * 2 + 1];
                float2 vs = make_float2(accS[m][nt][h * 2 + 0] + hx,
                                        accS[m][nt][h * 2 + 1] + hy);
                float2 vd = make_float2(accD[m][nt][h * 2 + 0] + hx,
                                        accD[m][nt][h * 2 + 1] + hy);
                *(float2*)&Ss[r * 128 + (col ^ key)] = vs;
                *(float2*)&Sd[r * 128 + (col ^ key)] = vd;
            }
        }
    __syncthreads();
    for (int i = tid; i < 32 * 32; i += 128) {
        int r = i >> 5, q = (i & 31) * 4;
        int e = e0 + r;
        if (e < E) {
            int key = (r & 7) << 2;
            int s = sI[r], d = dI[r];
            float4 vs = *(float4*)&Ss[r * 128 + (q ^ key)];
            float4 vd = *(float4*)&Sd[r * 128 + (q ^ key)];
            float4 bb = ldg4(&bias[q]);
            float4 ps = ldg4(&proj[(size_t)s * 128 + q]);
            float4 pd = ldg4(&proj[(size_t)d * 128 + q]);
            float4 os, od;
            os.x = fmaxf(vs.x + bb.x + ps.x, 0.f);
            os.y = fmaxf(vs.y + bb.y + ps.y, 0.f);
            os.z = fmaxf(vs.z + bb.z + ps.z, 0.f);
            os.w = fmaxf(vs.w + bb.w + ps.w, 0.f);
            od.x = fmaxf(vd.x + bb.x + pd.x, 0.f);
            od.y = fmaxf(vd.y + bb.y + pd.y, 0.f);
            od.z = fmaxf(vd.z + bb.z + pd.z, 0.f);
            od.w = fmaxf(vd.w + bb.w + pd.w, 0.f);
            *(float4*)&outS[(size_t)e * 128 + q] = os;
            *(float4*)&outD[(size_t)e * 128 + q] = od;
            red4(&sum2[(size_t)s * 128 + q], od);
            red4(&sum2[(size_t)d * 128 + q], os);
        }
    }
}

// ---------------------------------------------------------------------------
// Tensor-core layer-2 edge kernel. Coalesced staged epilogue.
// A (tf32, swizzled, stride 320): [0,128)=srcF, [128,256)=dstF, [256,320)=te2
// W rows: [0,128) head, [128,192) te (shared). Writes final output.
// ---------------------------------------------------------------------------
__global__ __launch_bounds__(128, 3) void k_layer2_t(
    const float* __restrict__ fS, const float* __restrict__ fD,
    const int* __restrict__ src, const int* __restrict__ dst, const float* __restrict__ ts,
    const float* __restrict__ W, const float* __restrict__ bias,
    const float* __restrict__ omega, const float* __restrict__ phase,
    const float* __restrict__ proj, float* __restrict__ outS, float* __restrict__ outD, int E) {
    const int AS = 320;
    extern __shared__ uint32_t sm[];
    uint32_t* A = sm;                  // 32*320 words; head reused as staging
    __shared__ int sI[32], dI[32];
    int tid = threadIdx.x, lane = tid & 31, warp = tid >> 5;
    int g = lane >> 2, t4 = lane & 3;
    int e0 = blockIdx.x * 32;
    int ntB = warp * 4;

    if (tid < 32) {
        int e = e0 + tid;
        bool ok = e < E;
        sI[tid] = ok ? __ldg(&src[e]) : 0;
        dI[tid] = ok ? __ldg(&dst[e]) : 0;
    }
    __syncthreads();

    // Fill A: srcF/dstF rows (64 float4 per edge)
    for (int i = tid; i < 32 * 64; i += 128) {
        int r = i >> 6, p = i & 63;
        int e = e0 + r;
        bool ok = e < E;
        float4 v = make_float4(0.f, 0.f, 0.f, 0.f);
        int col;
        if (p < 32) {
            col = p * 4;
            if (ok) v = ldg4(&fS[(size_t)e * 128 + p * 4]);
        } else {
            col = 128 + (p - 32) * 4;
            if (ok) v = ldg4(&fD[(size_t)e * 128 + (p - 32) * 4]);
        }
        uint4 u;
        u.x = f2tf(v.x); u.y = f2tf(v.y); u.z = f2tf(v.z); u.w = f2tf(v.w);
        *(uint4*)&A[r * AS + (col ^ ((r & 7) << 2))] = u;
    }
    // te2 cols [256,320)
    for (int i = tid; i < 32 * 16; i += 128) {
        int r = i >> 4, q = (i & 15) * 4;
        int e = e0 + r;
        float t = (e < E) ? __ldg(&ts[e]) : 0.f;
        uint4 u;
        u.x = f2tf(cosf(t * __ldg(&omega[q + 0]) + __ldg(&phase[q + 0])));
        u.y = f2tf(cosf(t * __ldg(&omega[q + 1]) + __ldg(&phase[q + 1])));
        u.z = f2tf(cosf(t * __ldg(&omega[q + 2]) + __ldg(&phase[q + 2])));
        u.w = f2tf(cosf(t * __ldg(&omega[q + 3]) + __ldg(&phase[q + 3])));
        *(uint4*)&A[r * AS + ((256 + q) ^ ((r & 7) << 2))] = u;
    }
    __syncthreads();

    float accS[2][4][4], accD[2][4][4], accH[2][4][4];
#pragma unroll
    for (int m = 0; m < 2; m++)
#pragma unroll
        for (int nt = 0; nt < 4; nt++)
#pragma unroll
            for (int k = 0; k < 4; k++) {
                accS[m][nt][k] = 0.f; accD[m][nt][k] = 0.f; accH[m][nt][k] = 0.f;
            }

    // Head: W rows [0,128); src = A cols k0, dst = A cols 128+k0
    for (int ks = 0; ks < 16; ks++) {
        int k0 = ks * 8;
        uint32_t aS4[2][4], aD4[2][4];
        ldA(aS4[0], A, AS, 0, k0, g, t4);
        ldA(aS4[1], A, AS, 16, k0, g, t4);
        ldA(aD4[0], A, AS, 0, 128 + k0, g, t4);
        ldA(aD4[1], A, AS, 16, 128 + k0, g, t4);
        const float* Wrow = &W[(size_t)(k0 + t4) * 128 + ntB * 8 + g];
#pragma unroll
        for (int nt = 0; nt < 4; nt++) {
            uint32_t bf[2];
            ldB(bf, Wrow, nt * 8);
            mma8(accS[0][nt], aS4[0], bf);
            mma8(accS[1][nt], aS4[1], bf);
            mma8(accD[0][nt], aD4[0], bf);
            mma8(accD[1][nt], aD4[1], bf);
        }
    }
    // te: W rows [128,192); A cols [256,320)
    for (int ks = 0; ks < 8; ks++) {
        int k0 = ks * 8;
        uint32_t aH4[2][4];
        ldA(aH4[0], A, AS, 0, 256 + k0, g, t4);
        ldA(aH4[1], A, AS, 16, 256 + k0, g, t4);
        const float* Wrow = &W[(size_t)(128 + k0 + t4) * 128 + ntB * 8 + g];
#pragma unroll
        for (int nt = 0; nt < 4; nt++) {
            uint32_t bf[2];
            ldB(bf, Wrow, nt * 8);
            mma8(accH[0][nt], aH4[0], bf);
            mma8(accH[1][nt], aH4[1], bf);
        }
    }

    // Stage + coalesced writeback
    __syncthreads();
    float* Ss = (float*)A;
    float* Sd = (float*)A + 32 * 128;
#pragma unroll
    for (int m = 0; m < 2; m++)
#pragma unroll
        for (int h = 0; h < 2; h++) {
            int r = m * 16 + h * 8 + g;
            int key = (r & 7) << 2;
#pragma unroll
            for (int nt = 0; nt < 4; nt++) {
                int col = (ntB + nt) * 8 + t4 * 2;
                float hx = accH[m][nt][h * 2 + 0], hy = accH[m][nt][h * 2 + 1];
                float2 vs = make_float2(accS[m][nt][h * 2 + 0] + hx,
                                        accS[m][nt][h * 2 + 1] + hy);
                float2 vd = make_float2(accD[m][nt][h * 2 + 0] + hx,
                                        accD[m][nt][h * 2 + 1] + hy);
                *(float2*)&Ss[r * 128 + (col ^ key)] = vs;
                *(float2*)&Sd[r * 128 + (col ^ key)] = vd;
            }
        }
    __syncthreads();
    for (int i = tid; i < 32 * 32; i += 128) {
        int r = i >> 5, q = (i & 31) * 4;
        int e = e0 + r;
        if (e < E) {
            int key = (r & 7) << 2;
            int s = sI[r], d = dI[r];
            float4 vs = *(float4*)&Ss[r * 128 + (q ^ key)];
            float4 vd = *(float4*)&Sd[r * 128 + (q ^ key)];
            float4 bb = ldg4(&bias[q]);
            float4 ps = ldg4(&proj[(size_t)s * 128 + q]);
            float4 pd = ldg4(&proj[(size_t)d * 128 + q]);
            float4 os, od;
            os.x = fmaxf(vs.x + bb.x + ps.x, 0.f);
            os.y = fmaxf(vs.y + bb.y + ps.y, 0.f);
            os.z = fmaxf(vs.z + bb.z + ps.z, 0.f);
            os.w = fmaxf(vs.w + bb.w + ps.w, 0.f);
            od.x = fmaxf(vd.x + bb.x + pd.x, 0.f);
            od.y = fmaxf(vd.y + bb.y + pd.y, 0.f);
            od.z = fmaxf(vd.z + bb.z + pd.z, 0.f);
            od.w = fmaxf(vd.w + bb.w + pd.w, 0.f);
            *(float4*)&outS[(size_t)e * 128 + q] = os;
            *(float4*)&outD[(size_t)e * 128 + q] = od;
        }
    }
}

// ---------------------------------------------------------------------------
extern "C" void kernel_launch(void* const* d_in, const int* in_sizes, int n_in,
                              void* d_out, int out_size) {
    const float* nfeat = (const float*)d_in[0];
    const float* efeat = (const float*)d_in[1];
    const int*   src   = (const int*)d_in[2];
    const int*   dst   = (const int*)d_in[3];
    const float* ts    = (const float*)d_in[4];
    const float* Ws1 = (const float*)d_in[5];
    const float* bs1 = (const float*)d_in[6];
    const float* Wn1 = (const float*)d_in[7];
    const float* bn1 = (const float*)d_in[8];
    const float* om1 = (const float*)d_in[9];
    const float* ph1 = (const float*)d_in[10];
    const float* Ws2 = (const float*)d_in[11];
    const float* bs2 = (const float*)d_in[12];
    const float* Wn2 = (const float*)d_in[13];
    const float* bn2 = (const float*)d_in[14];
    const float* om2 = (const float*)d_in[15];
    const float* ph2 = (const float*)d_in[16];

    int Nn = in_sizes[0] / 64;
    int E  = in_sizes[2];

    float *cnt, *s1, *s2, *proj, *sf, *df;
    cudaGetSymbolAddress((void**)&cnt,  g_cnt);
    cudaGetSymbolAddress((void**)&s1,   g_sum1);
    cudaGetSymbolAddress((void**)&s2,   g_sum2);
    cudaGetSymbolAddress((void**)&proj, g_proj);
    cudaGetSymbolAddress((void**)&sf,   g_srcF);
    cudaGetSymbolAddress((void**)&df,   g_dstF);

    float* outv = (float*)d_out;
    int nTileBlocks = (Nn + 31) / 32;
    int eTileBlocks = (E + 31) / 32;

    size_t smProj = (size_t)(32 * 128) * 4;   // 16 KB
    size_t smL1   = (size_t)(32 * 256) * 4;   // 32 KB
    size_t smL2   = (size_t)(32 * 320) * 4;   // 40 KB

    cudaFuncSetAttribute(k_proj_t,   cudaFuncAttributeMaxDynamicSharedMemorySize, (int)smProj);
    cudaFuncSetAttribute(k_layer1_t, cudaFuncAttributeMaxDynamicSharedMemorySize, (int)smL1);
    cudaFuncSetAttribute(k_layer2_t, cudaFuncAttributeMaxDynamicSharedMemorySize, (int)smL2);

    k_zero<<<2048, 256>>>(cnt, s1, s2, Nn);
    k_agg1<<<2048, 256>>>(nfeat, efeat, src, dst, s1, cnt, E);
    k_proj_t<<<nTileBlocks, 128, smProj>>>(s1, cnt, Wn1, bn1, proj, Nn);
    k_layer1_t<<<eTileBlocks, 128, smL1>>>(nfeat, efeat, src, dst, ts, Ws1, bs1, om1, ph1,
                                           proj, sf, df, s2, E);
    k_proj_t<<<nTileBlocks, 128, smProj>>>(s2, cnt, Wn2, bn2, proj, Nn);
    k_layer2_t<<<eTileBlocks, 128, smL2>>>(sf, df, src, dst, ts, Ws2, bs2, om2, ph2,
                                           proj, outv, outv + (size_t)E * 128, E);
}

// round 11
// speedup vs baseline: 3.1461x; 1.1833x over previous
#include <cuda_runtime.h>
#include <math.h>
#include <stdint.h>

// Problem sizes (fixed by the dataset)
#define NN 100000
#define EE 500000

// Scratch (device globals; allocation-free per harness rules)
__device__ float g_cnt[NN];
__device__ float g_sum1[(size_t)NN * 128];
__device__ float g_sum2[(size_t)NN * 128];
__device__ float g_proj[(size_t)NN * 128];
__device__ float g_srcF[(size_t)EE * 128];
__device__ float g_dstF[(size_t)EE * 128];

__device__ __forceinline__ float4 ldg4(const float* p) {
    return __ldg((const float4*)p);
}

__device__ __forceinline__ void red4(float* p, float4 v) {
    asm volatile("red.global.add.v4.f32 [%0], {%1,%2,%3,%4};"
                 :: "l"(p), "f"(v.x), "f"(v.y), "f"(v.z), "f"(v.w) : "memory");
}

// fp32 -> tf32 (round to nearest)
__device__ __forceinline__ uint32_t f2tf(float f) {
    uint32_t u;
    asm("cvt.rna.tf32.f32 %0, %1;" : "=r"(u) : "f"(f));
    return u;
}

// D += A(16x8) * B(8x8), tf32 inputs, f32 accum
__device__ __forceinline__ void mma8(float* c, const uint32_t* a, const uint32_t* b) {
    asm volatile(
        "mma.sync.aligned.m16n8k8.row.col.f32.tf32.tf32.f32 "
        "{%0,%1,%2,%3}, {%4,%5,%6,%7}, {%8,%9}, {%0,%1,%2,%3};"
        : "+f"(c[0]), "+f"(c[1]), "+f"(c[2]), "+f"(c[3])
        : "r"(a[0]), "r"(a[1]), "r"(a[2]), "r"(a[3]), "r"(b[0]), "r"(b[1]));
}

// Load A fragment (m16 x k8) from swizzled smem tile.
// swizzle: element (r, c) stored at col c ^ ((r&7)<<2). stride % 32 == 0.
__device__ __forceinline__ void ldA(uint32_t a[4], const uint32_t* As, int stride,
                                    int rowBase, int k0, int g, int t4) {
    int key = g << 2;
    const uint32_t* p0 = As + (size_t)(rowBase + g) * stride;
    const uint32_t* p1 = p0 + (size_t)8 * stride;
    int c0 = (k0 + t4) ^ key;
    int c1 = (k0 + 4 + t4) ^ key;
    a[0] = p0[c0];
    a[1] = p1[c0];
    a[2] = p0[c1];
    a[3] = p1[c1];
}

// Batched B fragments: all 4 n-tiles for one k-step, LDGs issued together.
__device__ __forceinline__ void ldB4(uint32_t bf[4][2], const float* __restrict__ Wrow) {
    float b0[4], b1[4];
#pragma unroll
    for (int nt = 0; nt < 4; nt++) b0[nt] = __ldg(&Wrow[nt * 8]);
#pragma unroll
    for (int nt = 0; nt < 4; nt++) b1[nt] = __ldg(&Wrow[nt * 8 + 4 * 128]);
#pragma unroll
    for (int nt = 0; nt < 4; nt++) {
        bf[nt][0] = f2tf(b0[nt]);
        bf[nt][1] = f2tf(b1[nt]);
    }
}

// ---------------------------------------------------------------------------
// Zero cnt + sum1 + sum2
// ---------------------------------------------------------------------------
__global__ void k_zero(float* cnt, float* s1, float* s2, int n) {
    int i = blockIdx.x * blockDim.x + threadIdx.x;
    int stride = gridDim.x * blockDim.x;
    int t4 = n * 32;
    float4 z = make_float4(0.f, 0.f, 0.f, 0.f);
    for (int j = i; j < t4; j += stride) {
        ((float4*)s1)[j] = z;
        ((float4*)s2)[j] = z;
    }
    for (int j = i; j < n; j += stride) cnt[j] = 0.f;
}

// ---------------------------------------------------------------------------
// Layer-1 aggregation (L2 atomics)
// ---------------------------------------------------------------------------
__global__ void k_agg1(const float* __restrict__ nfeat, const float* __restrict__ efeat,
                       const int* __restrict__ src, const int* __restrict__ dst,
                       float* sum1, float* cnt, int E) {
    int warp = (blockIdx.x * blockDim.x + threadIdx.x) >> 5;
    int lane = threadIdx.x & 31;
    int nw = (gridDim.x * blockDim.x) >> 5;
    for (int e = warp; e < E; e += nw) {
        int s = __ldg(&src[e]);
        int d = __ldg(&dst[e]);
        float4 vs, vd;
        int off;
        if (lane < 16) {
            off = lane * 4;
            vs = ldg4(&nfeat[(size_t)d * 64 + off]);
            vd = ldg4(&nfeat[(size_t)s * 64 + off]);
        } else {
            int q = (lane - 16) * 4;
            off = 64 + q;
            float4 ef = ldg4(&efeat[(size_t)e * 64 + q]);
            vs = ef; vd = ef;
        }
        red4(&sum1[(size_t)s * 128 + off], vs);
        red4(&sum1[(size_t)d * 128 + off], vd);
        if (lane == 0) {
            atomicAdd(&cnt[s], 1.f);
            atomicAdd(&cnt[d], 1.f);
        }
    }
}

// ---------------------------------------------------------------------------
// Tensor-core node projection: proj[n] = (sum[n]/max(cnt,1)) @ W[128,128] + b
// ---------------------------------------------------------------------------
__global__ __launch_bounds__(128, 4) void k_proj_t(
    const float* __restrict__ sum, const float* __restrict__ cnt,
    const float* __restrict__ W, const float* __restrict__ bias,
    float* __restrict__ proj, int Nn) {
    extern __shared__ uint32_t sm[];
    uint32_t* As = sm;                 // 32*128 words (reused as output staging)
    __shared__ float invS[32];
    int tid = threadIdx.x, lane = tid & 31, warp = tid >> 5;
    int g = lane >> 2, t4 = lane & 3;
    int n0 = blockIdx.x * 32;
    int ntB = warp * 4;

    if (tid < 32) {
        int n = n0 + tid;
        float c = 1.f;
        if (n < Nn) c = fmaxf(__ldg(&cnt[n]), 1.f);
        invS[tid] = 1.f / c;
    }
    __syncthreads();
    for (int i = tid; i < 32 * 32; i += 128) {
        int r = i >> 5, q = (i & 31) * 4;
        int n = n0 + r;
        float4 v = make_float4(0.f, 0.f, 0.f, 0.f);
        if (n < Nn) v = ldg4(&sum[(size_t)n * 128 + q]);
        float s = invS[r];
        uint4 u;
        u.x = f2tf(v.x * s); u.y = f2tf(v.y * s);
        u.z = f2tf(v.z * s); u.w = f2tf(v.w * s);
        *(uint4*)&As[r * 128 + (q ^ ((r & 7) << 2))] = u;
    }
    __syncthreads();

    float acc[2][4][4];
#pragma unroll
    for (int m = 0; m < 2; m++)
#pragma unroll
        for (int nt = 0; nt < 4; nt++)
#pragma unroll
            for (int k = 0; k < 4; k++) acc[m][nt][k] = 0.f;

    for (int ks = 0; ks < 16; ks++) {
        int k0 = ks * 8;
        uint32_t a[2][4];
        uint32_t bf[4][2];
        ldB4(bf, &W[(size_t)(k0 + t4) * 128 + ntB * 8 + g]);
        ldA(a[0], As, 128, 0, k0, g, t4);
        ldA(a[1], As, 128, 16, k0, g, t4);
#pragma unroll
        for (int nt = 0; nt < 4; nt++) {
            mma8(acc[0][nt], a[0], bf[nt]);
            mma8(acc[1][nt], a[1], bf[nt]);
        }
    }

    // Stage accumulators into smem (swizzled), then coalesced writeback
    __syncthreads();
    float* S = (float*)As;
#pragma unroll
    for (int m = 0; m < 2; m++)
#pragma unroll
        for (int h = 0; h < 2; h++) {
            int r = m * 16 + h * 8 + g;
            int key = (r & 7) << 2;
#pragma unroll
            for (int nt = 0; nt < 4; nt++) {
                int col = (ntB + nt) * 8 + t4 * 2;
                float2 v = make_float2(acc[m][nt][h * 2 + 0], acc[m][nt][h * 2 + 1]);
                *(float2*)&S[r * 128 + (col ^ key)] = v;
            }
        }
    __syncthreads();
    for (int i = tid; i < 32 * 32; i += 128) {
        int r = i >> 5, q = (i & 31) * 4;
        int n = n0 + r;
        if (n < Nn) {
            int key = (r & 7) << 2;
            float4 v = *(float4*)&S[r * 128 + (q ^ key)];
            float4 bb = ldg4(&bias[q]);
            float4 o;
            o.x = v.x + bb.x; o.y = v.y + bb.y; o.z = v.z + bb.z; o.w = v.w + bb.w;
            *(float4*)&proj[(size_t)n * 128 + q] = o;
        }
    }
}

// ---------------------------------------------------------------------------
// Tensor-core layer-1 edge kernel.
// Shared GEMM part first (acc1), copy acc1->acc2, then head part accumulates
// src into acc1 and dst into acc2 (saves 32 accumulator regs -> 4 blocks/SM).
// A (tf32, swizzled, stride 256): [0,64)=nfeat[src], [64,128)=nfeat[dst],
//                                 [128,192)=efeat, [192,256)=te
// W rows: [0,64) head (per src/dst), [64,192) shared. B direct from gmem.
// ---------------------------------------------------------------------------
__global__ __launch_bounds__(128, 4) void k_layer1_t(
    const float* __restrict__ nfeat, const float* __restrict__ efeat,
    const int* __restrict__ src, const int* __restrict__ dst, const float* __restrict__ ts,
    const float* __restrict__ W, const float* __restrict__ bias,
    const float* __restrict__ omega, const float* __restrict__ phase,
    const float* __restrict__ proj, float* __restrict__ outS, float* __restrict__ outD,
    float* __restrict__ sum2, int E) {
    const int AS = 256;
    extern __shared__ uint32_t sm[];
    uint32_t* A = sm;                  // 32*256 words; reused as 2x(32x128) staging
    __shared__ int sI[32], dI[32];
    __shared__ float tsS[32];
    int tid = threadIdx.x, lane = tid & 31, warp = tid >> 5;
    int g = lane >> 2, t4 = lane & 3;
    int e0 = blockIdx.x * 32;
    int ntB = warp * 4;

    if (tid < 32) {
        int e = e0 + tid;
        bool ok = e < E;
        sI[tid] = ok ? __ldg(&src[e]) : 0;
        dI[tid] = ok ? __ldg(&dst[e]) : 0;
        tsS[tid] = ok ? __ldg(&ts[e]) : 0.f;
    }
    __syncthreads();

    // Fill A (48 float4 per edge), converted to tf32, swizzled.
    for (int i = tid; i < 32 * 48; i += 128) {
        int r = i / 48, p = i % 48;
        int e = e0 + r;
        bool ok = e < E;
        float4 v = make_float4(0.f, 0.f, 0.f, 0.f);
        int col;
        if (p < 16) {
            col = p * 4;
            if (ok) v = ldg4(&nfeat[(size_t)sI[r] * 64 + p * 4]);
        } else if (p < 32) {
            col = 64 + (p - 16) * 4;
            if (ok) v = ldg4(&nfeat[(size_t)dI[r] * 64 + (p - 16) * 4]);
        } else {
            col = 128 + (p - 32) * 4;
            if (ok) v = ldg4(&efeat[(size_t)e * 64 + (p - 32) * 4]);
        }
        uint4 u;
        u.x = f2tf(v.x); u.y = f2tf(v.y); u.z = f2tf(v.z); u.w = f2tf(v.w);
        *(uint4*)&A[r * AS + (col ^ ((r & 7) << 2))] = u;
    }
    // te cols [192,256)
    for (int i = tid; i < 32 * 16; i += 128) {
        int r = i >> 4, q = (i & 15) * 4;
        float t = tsS[r];
        uint4 u;
        u.x = f2tf(cosf(t * __ldg(&omega[q + 0]) + __ldg(&phase[q + 0])));
        u.y = f2tf(cosf(t * __ldg(&omega[q + 1]) + __ldg(&phase[q + 1])));
        u.z = f2tf(cosf(t * __ldg(&omega[q + 2]) + __ldg(&phase[q + 2])));
        u.w = f2tf(cosf(t * __ldg(&omega[q + 3]) + __ldg(&phase[q + 3])));
        *(uint4*)&A[r * AS + ((192 + q) ^ ((r & 7) << 2))] = u;
    }
    __syncthreads();

    float acc1[2][4][4], acc2[2][4][4];
#pragma unroll
    for (int m = 0; m < 2; m++)
#pragma unroll
        for (int nt = 0; nt < 4; nt++)
#pragma unroll
            for (int k = 0; k < 4; k++) acc1[m][nt][k] = 0.f;

    // Shared part: W rows [64,192); A cols [128,256) -> acc1
    for (int ks = 0; ks < 16; ks++) {
        int k0 = ks * 8;
        uint32_t aH4[2][4];
        uint32_t bf[4][2];
        ldB4(bf, &W[(size_t)(64 + k0 + t4) * 128 + ntB * 8 + g]);
        ldA(aH4[0], A, AS, 0, 128 + k0, g, t4);
        ldA(aH4[1], A, AS, 16, 128 + k0, g, t4);
#pragma unroll
        for (int nt = 0; nt < 4; nt++) {
            mma8(acc1[0][nt], aH4[0], bf[nt]);
            mma8(acc1[1][nt], aH4[1], bf[nt]);
        }
    }
    // acc2 starts as a copy of the shared part
#pragma unroll
    for (int m = 0; m < 2; m++)
#pragma unroll
        for (int nt = 0; nt < 4; nt++)
#pragma unroll
            for (int k = 0; k < 4; k++) acc2[m][nt][k] = acc1[m][nt][k];

    // Head part: W rows [0,64); src = A cols k0 -> acc1, dst = A cols 64+k0 -> acc2
    for (int ks = 0; ks < 8; ks++) {
        int k0 = ks * 8;
        uint32_t aS4[2][4], aD4[2][4];
        uint32_t bf[4][2];
        ldB4(bf, &W[(size_t)(k0 + t4) * 128 + ntB * 8 + g]);
        ldA(aS4[0], A, AS, 0, k0, g, t4);
        ldA(aS4[1], A, AS, 16, k0, g, t4);
        ldA(aD4[0], A, AS, 0, 64 + k0, g, t4);
        ldA(aD4[1], A, AS, 16, 64 + k0, g, t4);
#pragma unroll
        for (int nt = 0; nt < 4; nt++) {
            mma8(acc1[0][nt], aS4[0], bf[nt]);
            mma8(acc1[1][nt], aS4[1], bf[nt]);
            mma8(acc2[0][nt], aD4[0], bf[nt]);
            mma8(acc2[1][nt], aD4[1], bf[nt]);
        }
    }

    // Stage into smem (A is dead), then coalesced writeback + fused sum2
    __syncthreads();
    float* Ss = (float*)A;
    float* Sd = (float*)A + 32 * 128;
#pragma unroll
    for (int m = 0; m < 2; m++)
#pragma unroll
        for (int h = 0; h < 2; h++) {
            int r = m * 16 + h * 8 + g;
            int key = (r & 7) << 2;
#pragma unroll
            for (int nt = 0; nt < 4; nt++) {
                int col = (ntB + nt) * 8 + t4 * 2;
                float2 vs = make_float2(acc1[m][nt][h * 2 + 0], acc1[m][nt][h * 2 + 1]);
                float2 vd = make_float2(acc2[m][nt][h * 2 + 0], acc2[m][nt][h * 2 + 1]);
                *(float2*)&Ss[r * 128 + (col ^ key)] = vs;
                *(float2*)&Sd[r * 128 + (col ^ key)] = vd;
            }
        }
    __syncthreads();
    for (int i = tid; i < 32 * 32; i += 128) {
        int r = i >> 5, q = (i & 31) * 4;
        int e = e0 + r;
        if (e < E) {
            int key = (r & 7) << 2;
            int s = sI[r], d = dI[r];
            float4 vs = *(float4*)&Ss[r * 128 + (q ^ key)];
            float4 vd = *(float4*)&Sd[r * 128 + (q ^ key)];
            float4 bb = ldg4(&bias[q]);
            float4 ps = ldg4(&proj[(size_t)s * 128 + q]);
            float4 pd = ldg4(&proj[(size_t)d * 128 + q]);
            float4 os, od;
            os.x = fmaxf(vs.x + bb.x + ps.x, 0.f);
            os.y = fmaxf(vs.y + bb.y + ps.y, 0.f);
            os.z = fmaxf(vs.z + bb.z + ps.z, 0.f);
            os.w = fmaxf(vs.w + bb.w + ps.w, 0.f);
            od.x = fmaxf(vd.x + bb.x + pd.x, 0.f);
            od.y = fmaxf(vd.y + bb.y + pd.y, 0.f);
            od.z = fmaxf(vd.z + bb.z + pd.z, 0.f);
            od.w = fmaxf(vd.w + bb.w + pd.w, 0.f);
            *(float4*)&outS[(size_t)e * 128 + q] = os;
            *(float4*)&outD[(size_t)e * 128 + q] = od;
            red4(&sum2[(size_t)s * 128 + q], od);
            red4(&sum2[(size_t)d * 128 + q], os);
        }
    }
}

// ---------------------------------------------------------------------------
// Tensor-core layer-2 edge kernel. Same acc1/acc2 restructure.
// A (tf32, swizzled, stride 320): [0,128)=srcF, [128,256)=dstF, [256,320)=te2
// W rows: [0,128) head, [128,192) te (shared). Writes final output.
// ---------------------------------------------------------------------------
__global__ __launch_bounds__(128, 4) void k_layer2_t(
    const float* __restrict__ fS, const float* __restrict__ fD,
    const int* __restrict__ src, const int* __restrict__ dst, const float* __restrict__ ts,
    const float* __restrict__ W, const float* __restrict__ bias,
    const float* __restrict__ omega, const float* __restrict__ phase,
    const float* __restrict__ proj, float* __restrict__ outS, float* __restrict__ outD, int E) {
    const int AS = 320;
    extern __shared__ uint32_t sm[];
    uint32_t* A = sm;                  // 32*320 words; head reused as staging
    __shared__ int sI[32], dI[32];
    int tid = threadIdx.x, lane = tid & 31, warp = tid >> 5;
    int g = lane >> 2, t4 = lane & 3;
    int e0 = blockIdx.x * 32;
    int ntB = warp * 4;

    if (tid < 32) {
        int e = e0 + tid;
        bool ok = e < E;
        sI[tid] = ok ? __ldg(&src[e]) : 0;
        dI[tid] = ok ? __ldg(&dst[e]) : 0;
    }
    __syncthreads();

    // Fill A: srcF/dstF rows (64 float4 per edge)
    for (int i = tid; i < 32 * 64; i += 128) {
        int r = i >> 6, p = i & 63;
        int e = e0 + r;
        bool ok = e < E;
        float4 v = make_float4(0.f, 0.f, 0.f, 0.f);
        int col;
        if (p < 32) {
            col = p * 4;
            if (ok) v = ldg4(&fS[(size_t)e * 128 + p * 4]);
        } else {
            col = 128 + (p - 32) * 4;
            if (ok) v = ldg4(&fD[(size_t)e * 128 + (p - 32) * 4]);
        }
        uint4 u;
        u.x = f2tf(v.x); u.y = f2tf(v.y); u.z = f2tf(v.z); u.w = f2tf(v.w);
        *(uint4*)&A[r * AS + (col ^ ((r & 7) << 2))] = u;
    }
    // te2 cols [256,320)
    for (int i = tid; i < 32 * 16; i += 128) {
        int r = i >> 4, q = (i & 15) * 4;
        int e = e0 + r;
        float t = (e < E) ? __ldg(&ts[e]) : 0.f;
        uint4 u;
        u.x = f2tf(cosf(t * __ldg(&omega[q + 0]) + __ldg(&phase[q + 0])));
        u.y = f2tf(cosf(t * __ldg(&omega[q + 1]) + __ldg(&phase[q + 1])));
        u.z = f2tf(cosf(t * __ldg(&omega[q + 2]) + __ldg(&phase[q + 2])));
        u.w = f2tf(cosf(t * __ldg(&omega[q + 3]) + __ldg(&phase[q + 3])));
        *(uint4*)&A[r * AS + ((256 + q) ^ ((r & 7) << 2))] = u;
    }
    __syncthreads();

    float acc1[2][4][4], acc2[2][4][4];
#pragma unroll
    for (int m = 0; m < 2; m++)
#pragma unroll
        for (int nt = 0; nt < 4; nt++)
#pragma unroll
            for (int k = 0; k < 4; k++) acc1[m][nt][k] = 0.f;

    // Shared te part: W rows [128,192); A cols [256,320) -> acc1
    for (int ks = 0; ks < 8; ks++) {
        int k0 = ks * 8;
        uint32_t aH4[2][4];
        uint32_t bf[4][2];
        ldB4(bf, &W[(size_t)(128 + k0 + t4) * 128 + ntB * 8 + g]);
        ldA(aH4[0], A, AS, 0, 256 + k0, g, t4);
        ldA(aH4[1], A, AS, 16, 256 + k0, g, t4);
#pragma unroll
        for (int nt = 0; nt < 4; nt++) {
            mma8(acc1[0][nt], aH4[0], bf[nt]);
            mma8(acc1[1][nt], aH4[1], bf[nt]);
        }
    }
#pragma unroll
    for (int m = 0; m < 2; m++)
#pragma unroll
        for (int nt = 0; nt < 4; nt++)
#pragma unroll
            for (int k = 0; k < 4; k++) acc2[m][nt][k] = acc1[m][nt][k];

    // Head: W rows [0,128); src = A cols k0 -> acc1, dst = A cols 128+k0 -> acc2
    for (int ks = 0; ks < 16; ks++) {
        int k0 = ks * 8;
        uint32_t aS4[2][4], aD4[2][4];
        uint32_t bf[4][2];
        ldB4(bf, &W[(size_t)(k0 + t4) * 128 + ntB * 8 + g]);
        ldA(aS4[0], A, AS, 0, k0, g, t4);
        ldA(aS4[1], A, AS, 16, k0, g, t4);
        ldA(aD4[0], A, AS, 0, 128 + k0, g, t4);
        ldA(aD4[1], A, AS, 16, 128 + k0, g, t4);
#pragma unroll
        for (int nt = 0; nt < 4; nt++) {
            mma8(acc1[0][nt], aS4[0], bf[nt]);
            mma8(acc1[1][nt], aS4[1], bf[nt]);
            mma8(acc2[0][nt], aD4[0], bf[nt]);
            mma8(acc2[1][nt], aD4[1], bf[nt]);
        }
    }

    // Stage + coalesced writeback
    __syncthreads();
    float* Ss = (float*)A;
    float* Sd = (float*)A + 32 * 128;
#pragma unroll
    for (int m = 0; m < 2; m++)
#pragma unroll
        for (int h = 0; h < 2; h++) {
            int r = m * 16 + h * 8 + g;
            int key = (r & 7) << 2;
#pragma unroll
            for (int nt = 0; nt < 4; nt++) {
                int col = (ntB + nt) * 8 + t4 * 2;
                float2 vs = make_float2(acc1[m][nt][h * 2 + 0], acc1[m][nt][h * 2 + 1]);
                float2 vd = make_float2(acc2[m][nt][h * 2 + 0], acc2[m][nt][h * 2 + 1]);
                *(float2*)&Ss[r * 128 + (col ^ key)] = vs;
                *(float2*)&Sd[r * 128 + (col ^ key)] = vd;
            }
        }
    __syncthreads();
    for (int i = tid; i < 32 * 32; i += 128) {
        int r = i >> 5, q = (i & 31) * 4;
        int e = e0 + r;
        if (e < E) {
            int key = (r & 7) << 2;
            int s = sI[r], d = dI[r];
            float4 vs = *(float4*)&Ss[r * 128 + (q ^ key)];
            float4 vd = *(float4*)&Sd[r * 128 + (q ^ key)];
            float4 bb = ldg4(&bias[q]);
            float4 ps = ldg4(&proj[(size_t)s * 128 + q]);
            float4 pd = ldg4(&proj[(size_t)d * 128 + q]);
            float4 os, od;
            os.x = fmaxf(vs.x + bb.x + ps.x, 0.f);
            os.y = fmaxf(vs.y + bb.y + ps.y, 0.f);
            os.z = fmaxf(vs.z + bb.z + ps.z, 0.f);
            os.w = fmaxf(vs.w + bb.w + ps.w, 0.f);
            od.x = fmaxf(vd.x + bb.x + pd.x, 0.f);
            od.y = fmaxf(vd.y + bb.y + pd.y, 0.f);
            od.z = fmaxf(vd.z + bb.z + pd.z, 0.f);
            od.w = fmaxf(vd.w + bb.w + pd.w, 0.f);
            *(float4*)&outS[(size_t)e * 128 + q] = os;
            *(float4*)&outD[(size_t)e * 128 + q] = od;
        }
    }
}

// ---------------------------------------------------------------------------
extern "C" void kernel_launch(void* const* d_in, const int* in_sizes, int n_in,
                              void* d_out, int out_size) {
    const float* nfeat = (const float*)d_in[0];
    const float* efeat = (const float*)d_in[1];
    const int*   src   = (const int*)d_in[2];
    const int*   dst   = (const int*)d_in[3];
    const float* ts    = (const float*)d_in[4];
    const float* Ws1 = (const float*)d_in[5];
    const float* bs1 = (const float*)d_in[6];
    const float* Wn1 = (const float*)d_in[7];
    const float* bn1 = (const float*)d_in[8];
    const float* om1 = (const float*)d_in[9];
    const float* ph1 = (const float*)d_in[10];
    const float* Ws2 = (const float*)d_in[11];
    const float* bs2 = (const float*)d_in[12];
    const float* Wn2 = (const float*)d_in[13];
    const float* bn2 = (const float*)d_in[14];
    const float* om2 = (const float*)d_in[15];
    const float* ph2 = (const float*)d_in[16];

    int Nn = in_sizes[0] / 64;
    int E  = in_sizes[2];

    float *cnt, *s1, *s2, *proj, *sf, *df;
    cudaGetSymbolAddress((void**)&cnt,  g_cnt);
    cudaGetSymbolAddress((void**)&s1,   g_sum1);
    cudaGetSymbolAddress((void**)&s2,   g_sum2);
    cudaGetSymbolAddress((void**)&proj, g_proj);
    cudaGetSymbolAddress((void**)&sf,   g_srcF);
    cudaGetSymbolAddress((void**)&df,   g_dstF);

    float* outv = (float*)d_out;
    int nTileBlocks = (Nn + 31) / 32;
    int eTileBlocks = (E + 31) / 32;

    size_t smProj = (size_t)(32 * 128) * 4;   // 16 KB
    size_t smL1   = (size_t)(32 * 256) * 4;   // 32 KB
    size_t smL2   = (size_t)(32 * 320) * 4;   // 40 KB

    cudaFuncSetAttribute(k_proj_t,   cudaFuncAttributeMaxDynamicSharedMemorySize, (int)smProj);
    cudaFuncSetAttribute(k_layer1_t, cudaFuncAttributeMaxDynamicSharedMemorySize, (int)smL1);
    cudaFuncSetAttribute(k_layer2_t, cudaFuncAttributeMaxDynamicSharedMemorySize, (int)smL2);

    k_zero<<<2048, 256>>>(cnt, s1, s2, Nn);
    k_agg1<<<2048, 256>>>(nfeat, efeat, src, dst, s1, cnt, E);
    k_proj_t<<<nTileBlocks, 128, smProj>>>(s1, cnt, Wn1, bn1, proj, Nn);
    k_layer1_t<<<eTileBlocks, 128, smL1>>>(nfeat, efeat, src, dst, ts, Ws1, bs1, om1, ph1,
                                           proj, sf, df, s2, E);
    k_proj_t<<<nTileBlocks, 128, smProj>>>(s2, cnt, Wn2, bn2, proj, Nn);
    k_layer2_t<<<eTileBlocks, 128, smL2>>>(sf, df, src, dst, ts, Ws2, bs2, om2, ph2,
                                           proj, outv, outv + (size_t)E * 128, E);
}

// round 12
// speedup vs baseline: 3.7624x; 1.1959x over previous
#include <cuda_runtime.h>
#include <cuda_fp16.h>
#include <math.h>
#include <stdint.h>

// Problem sizes (fixed by the dataset)
#define NN 100000
#define EE 500000

// Scratch (device globals; allocation-free per harness rules)
__device__ float g_cnt[NN];
__device__ float g_sum1[(size_t)NN * 128];
__device__ float g_sum2[(size_t)NN * 128];
__device__ float g_proj[(size_t)NN * 128];
__device__ __half g_srcF[(size_t)EE * 128];
__device__ __half g_dstF[(size_t)EE * 128];
// W_self transposed + half2-packed: WT[n*96 + kw] = half2(W[2kw][n], W[2kw+1][n])
__device__ uint32_t g_WT1[128 * 96];
__device__ uint32_t g_WT2[128 * 96];

__device__ __forceinline__ float4 ldg4(const float* p) {
    return __ldg((const float4*)p);
}

__device__ __forceinline__ void red4(float* p, float4 v) {
    asm volatile("red.global.add.v4.f32 [%0], {%1,%2,%3,%4};"
                 :: "l"(p), "f"(v.x), "f"(v.y), "f"(v.z), "f"(v.w) : "memory");
}

// fp32 -> tf32 (round to nearest) — proj kernel only
__device__ __forceinline__ uint32_t f2tf(float f) {
    uint32_t u;
    asm("cvt.rna.tf32.f32 %0, %1;" : "=r"(u) : "f"(f));
    return u;
}

// pack two fp32 into half2 word (lo = first/even k, hi = second/odd k)
__device__ __forceinline__ uint32_t packh2(float lo, float hi) {
    __half2 h = __floats2half2_rn(lo, hi);
    return *reinterpret_cast<uint32_t*>(&h);
}

// tf32 m16n8k8 (proj kernel)
__device__ __forceinline__ void mma8(float* c, const uint32_t* a, const uint32_t* b) {
    asm volatile(
        "mma.sync.aligned.m16n8k8.row.col.f32.tf32.tf32.f32 "
        "{%0,%1,%2,%3}, {%4,%5,%6,%7}, {%8,%9}, {%0,%1,%2,%3};"
        : "+f"(c[0]), "+f"(c[1]), "+f"(c[2]), "+f"(c[3])
        : "r"(a[0]), "r"(a[1]), "r"(a[2]), "r"(a[3]), "r"(b[0]), "r"(b[1]));
}

// fp16 m16n8k16, fp32 accumulate (edge kernels)
__device__ __forceinline__ void mma16(float* c, const uint32_t* a, const uint32_t* b) {
    asm volatile(
        "mma.sync.aligned.m16n8k16.row.col.f32.f16.f16.f32 "
        "{%0,%1,%2,%3}, {%4,%5,%6,%7}, {%8,%9}, {%0,%1,%2,%3};"
        : "+f"(c[0]), "+f"(c[1]), "+f"(c[2]), "+f"(c[3])
        : "r"(a[0]), "r"(a[1]), "r"(a[2]), "r"(a[3]), "r"(b[0]), "r"(b[1]));
}

// Load A fragment from swizzled smem tile of 32-bit words.
// Word (r, c) stored at col c ^ ((r&7)<<2). stride % 32 == 0.
// tf32: words are k-scalars (k8 step). fp16: words are k-pairs (k16 step).
__device__ __forceinline__ void ldA(uint32_t a[4], const uint32_t* As, int stride,
                                    int rowBase, int c0base, int g, int t4) {
    int key = g << 2;
    const uint32_t* p0 = As + (size_t)(rowBase + g) * stride;
    const uint32_t* p1 = p0 + (size_t)8 * stride;
    int c0 = (c0base + t4) ^ key;
    int c1 = (c0base + 4 + t4) ^ key;
    a[0] = p0[c0];
    a[1] = p1[c0];
    a[2] = p0[c1];
    a[3] = p1[c1];
}

// Batched half2 B fragments for 4 n-tiles, one k16 step, from transposed WT.
// WTp = &WT[(ntB*8+g)*96 + kw0 + t4]; n-tile stride = 8 rows * 96 words.
__device__ __forceinline__ void ldB4h(uint32_t bf[4][2], const uint32_t* __restrict__ WTp) {
#pragma unroll
    for (int nt = 0; nt < 4; nt++) bf[nt][0] = __ldg(WTp + nt * 8 * 96);
#pragma unroll
    for (int nt = 0; nt < 4; nt++) bf[nt][1] = __ldg(WTp + nt * 8 * 96 + 4);
}

// ---------------------------------------------------------------------------
// One-time W_self transpose + half2 pack (per launch; tiny)
// WT[n*96+kw] = half2(W[2kw*128+n], W[(2kw+1)*128+n]), K=192, N=128
// ---------------------------------------------------------------------------
__global__ void k_prepW(const float* __restrict__ Ws1, const float* __restrict__ Ws2,
                        uint32_t* wt1, uint32_t* wt2) {
    int i = blockIdx.x * blockDim.x + threadIdx.x;
    if (i < 128 * 96) {
        int n = i / 96, kw = i % 96;
        wt1[i] = packh2(__ldg(&Ws1[(size_t)(2 * kw) * 128 + n]),
                        __ldg(&Ws1[(size_t)(2 * kw + 1) * 128 + n]));
        wt2[i] = packh2(__ldg(&Ws2[(size_t)(2 * kw) * 128 + n]),
                        __ldg(&Ws2[(size_t)(2 * kw + 1) * 128 + n]));
    }
}

// ---------------------------------------------------------------------------
// Zero cnt + sum1 + sum2
// ---------------------------------------------------------------------------
__global__ void k_zero(float* cnt, float* s1, float* s2, int n) {
    int i = blockIdx.x * blockDim.x + threadIdx.x;
    int stride = gridDim.x * blockDim.x;
    int t4 = n * 32;
    float4 z = make_float4(0.f, 0.f, 0.f, 0.f);
    for (int j = i; j < t4; j += stride) {
        ((float4*)s1)[j] = z;
        ((float4*)s2)[j] = z;
    }
    for (int j = i; j < n; j += stride) cnt[j] = 0.f;
}

// ---------------------------------------------------------------------------
// Layer-1 aggregation (L2 atomics)
// ---------------------------------------------------------------------------
__global__ void k_agg1(const float* __restrict__ nfeat, const float* __restrict__ efeat,
                       const int* __restrict__ src, const int* __restrict__ dst,
                       float* sum1, float* cnt, int E) {
    int warp = (blockIdx.x * blockDim.x + threadIdx.x) >> 5;
    int lane = threadIdx.x & 31;
    int nw = (gridDim.x * blockDim.x) >> 5;
    for (int e = warp; e < E; e += nw) {
        int s = __ldg(&src[e]);
        int d = __ldg(&dst[e]);
        float4 vs, vd;
        int off;
        if (lane < 16) {
            off = lane * 4;
            vs = ldg4(&nfeat[(size_t)d * 64 + off]);
            vd = ldg4(&nfeat[(size_t)s * 64 + off]);
        } else {
            int q = (lane - 16) * 4;
            off = 64 + q;
            float4 ef = ldg4(&efeat[(size_t)e * 64 + q]);
            vs = ef; vd = ef;
        }
        red4(&sum1[(size_t)s * 128 + off], vs);
        red4(&sum1[(size_t)d * 128 + off], vd);
        if (lane == 0) {
            atomicAdd(&cnt[s], 1.f);
            atomicAdd(&cnt[d], 1.f);
        }
    }
}

// ---------------------------------------------------------------------------
// Tensor-core node projection (tf32): proj[n] = (sum[n]/max(cnt,1)) @ W + b
// ---------------------------------------------------------------------------
__global__ __launch_bounds__(128, 4) void k_proj_t(
    const float* __restrict__ sum, const float* __restrict__ cnt,
    const float* __restrict__ W, const float* __restrict__ bias,
    float* __restrict__ proj, int Nn) {
    extern __shared__ uint32_t sm[];
    uint32_t* As = sm;                 // 32*128 words (reused as output staging)
    __shared__ float invS[32];
    int tid = threadIdx.x, lane = tid & 31, warp = tid >> 5;
    int g = lane >> 2, t4 = lane & 3;
    int n0 = blockIdx.x * 32;
    int ntB = warp * 4;

    if (tid < 32) {
        int n = n0 + tid;
        float c = 1.f;
        if (n < Nn) c = fmaxf(__ldg(&cnt[n]), 1.f);
        invS[tid] = 1.f / c;
    }
    __syncthreads();
    for (int i = tid; i < 32 * 32; i += 128) {
        int r = i >> 5, q = (i & 31) * 4;
        int n = n0 + r;
        float4 v = make_float4(0.f, 0.f, 0.f, 0.f);
        if (n < Nn) v = ldg4(&sum[(size_t)n * 128 + q]);
        float s = invS[r];
        uint4 u;
        u.x = f2tf(v.x * s); u.y = f2tf(v.y * s);
        u.z = f2tf(v.z * s); u.w = f2tf(v.w * s);
        *(uint4*)&As[r * 128 + (q ^ ((r & 7) << 2))] = u;
    }
    __syncthreads();

    float acc[2][4][4];
#pragma unroll
    for (int m = 0; m < 2; m++)
#pragma unroll
        for (int nt = 0; nt < 4; nt++)
#pragma unroll
            for (int k = 0; k < 4; k++) acc[m][nt][k] = 0.f;

    for (int ks = 0; ks < 16; ks++) {
        int k0 = ks * 8;
        uint32_t a[2][4];
        uint32_t bf[4][2];
        const float* Wrow = &W[(size_t)(k0 + t4) * 128 + ntB * 8 + g];
#pragma unroll
        for (int nt = 0; nt < 4; nt++) bf[nt][0] = f2tf(__ldg(&Wrow[nt * 8]));
#pragma unroll
        for (int nt = 0; nt < 4; nt++) bf[nt][1] = f2tf(__ldg(&Wrow[nt * 8 + 4 * 128]));
        ldA(a[0], As, 128, 0, k0, g, t4);
        ldA(a[1], As, 128, 16, k0, g, t4);
#pragma unroll
        for (int nt = 0; nt < 4; nt++) {
            mma8(acc[0][nt], a[0], bf[nt]);
            mma8(acc[1][nt], a[1], bf[nt]);
        }
    }

    __syncthreads();
    float* S = (float*)As;
#pragma unroll
    for (int m = 0; m < 2; m++)
#pragma unroll
        for (int h = 0; h < 2; h++) {
            int r = m * 16 + h * 8 + g;
            int key = (r & 7) << 2;
#pragma unroll
            for (int nt = 0; nt < 4; nt++) {
                int col = (ntB + nt) * 8 + t4 * 2;
                float2 v = make_float2(acc[m][nt][h * 2 + 0], acc[m][nt][h * 2 + 1]);
                *(float2*)&S[r * 128 + (col ^ key)] = v;
            }
        }
    __syncthreads();
    for (int i = tid; i < 32 * 32; i += 128) {
        int r = i >> 5, q = (i & 31) * 4;
        int n = n0 + r;
        if (n < Nn) {
            int key = (r & 7) << 2;
            float4 v = *(float4*)&S[r * 128 + (q ^ key)];
            float4 bb = ldg4(&bias[q]);
            float4 o;
            o.x = v.x + bb.x; o.y = v.y + bb.y; o.z = v.z + bb.z; o.w = v.w + bb.w;
            *(float4*)&proj[(size_t)n * 128 + q] = o;
        }
    }
}

// ---------------------------------------------------------------------------
// fp16 tensor-core layer-1 edge kernel.
// A (half2 words, swizzled, word-stride 128):
//   words [0,32)=nfeat[src], [32,64)=nfeat[dst], [64,96)=efeat, [96,128)=te
// WT rows (kw): head = kw [0,32), shared = kw [32,96).
// acc1 = src result, acc2 = dst result (shared part computed once, copied).
// ---------------------------------------------------------------------------
__global__ __launch_bounds__(128, 4) void k_layer1_t(
    const float* __restrict__ nfeat, const float* __restrict__ efeat,
    const int* __restrict__ src, const int* __restrict__ dst, const float* __restrict__ ts,
    const uint32_t* __restrict__ WT, const float* __restrict__ bias,
    const float* __restrict__ omega, const float* __restrict__ phase,
    const float* __restrict__ proj, __half* __restrict__ outS, __half* __restrict__ outD,
    float* __restrict__ sum2, int E) {
    const int AS = 128;  // words per edge row
    extern __shared__ uint32_t sm[];
    uint32_t* A = sm;    // 32*128 words = 16KB; staging needs 32KB (smem = 32KB)
    __shared__ int sI[32], dI[32];
    __shared__ float tsS[32];
    int tid = threadIdx.x, lane = tid & 31, warp = tid >> 5;
    int g = lane >> 2, t4 = lane & 3;
    int e0 = blockIdx.x * 32;
    int ntB = warp * 4;

    if (tid < 32) {
        int e = e0 + tid;
        bool ok = e < E;
        sI[tid] = ok ? __ldg(&src[e]) : 0;
        dI[tid] = ok ? __ldg(&dst[e]) : 0;
        tsS[tid] = ok ? __ldg(&ts[e]) : 0.f;
    }
    __syncthreads();

    // Fill A: 48 float4-groups per edge -> half2 pairs
    for (int i = tid; i < 32 * 48; i += 128) {
        int r = i / 48, p = i % 48;
        int e = e0 + r;
        bool ok = e < E;
        float4 v = make_float4(0.f, 0.f, 0.f, 0.f);
        int col;  // half-element column, multiple of 4
        if (p < 16) {
            col = p * 4;
            if (ok) v = ldg4(&nfeat[(size_t)sI[r] * 64 + p * 4]);
        } else if (p < 32) {
            col = 64 + (p - 16) * 4;
            if (ok) v = ldg4(&nfeat[(size_t)dI[r] * 64 + (p - 16) * 4]);
        } else {
            col = 128 + (p - 32) * 4;
            if (ok) v = ldg4(&efeat[(size_t)e * 64 + (p - 32) * 4]);
        }
        uint2 u;
        u.x = packh2(v.x, v.y);
        u.y = packh2(v.z, v.w);
        *(uint2*)&A[r * AS + ((col >> 1) ^ ((r & 7) << 2))] = u;
    }
    // te: half cols [192,256) = words [96,128)
    for (int i = tid; i < 32 * 16; i += 128) {
        int r = i >> 4, q = (i & 15) * 4;
        float t = tsS[r];
        float c0 = cosf(t * __ldg(&omega[q + 0]) + __ldg(&phase[q + 0]));
        float c1 = cosf(t * __ldg(&omega[q + 1]) + __ldg(&phase[q + 1]));
        float c2 = cosf(t * __ldg(&omega[q + 2]) + __ldg(&phase[q + 2]));
        float c3 = cosf(t * __ldg(&omega[q + 3]) + __ldg(&phase[q + 3]));
        uint2 u;
        u.x = packh2(c0, c1);
        u.y = packh2(c2, c3);
        *(uint2*)&A[r * AS + ((96 + (q >> 1)) ^ ((r & 7) << 2))] = u;
    }
    __syncthreads();

    float acc1[2][4][4], acc2[2][4][4];
#pragma unroll
    for (int m = 0; m < 2; m++)
#pragma unroll
        for (int nt = 0; nt < 4; nt++)
#pragma unroll
            for (int k = 0; k < 4; k++) acc1[m][nt][k] = 0.f;

    const uint32_t* WTbase = WT + (size_t)(ntB * 8 + g) * 96 + t4;

    // Shared part: A words [64,128), WT kw [32,96): 8 k16 steps -> acc1
    for (int ks = 0; ks < 8; ks++) {
        uint32_t aH4[2][4];
        uint32_t bf[4][2];
        ldB4h(bf, WTbase + 32 + ks * 8);
        ldA(aH4[0], A, AS, 0, 64 + ks * 8, g, t4);
        ldA(aH4[1], A, AS, 16, 64 + ks * 8, g, t4);
#pragma unroll
        for (int nt = 0; nt < 4; nt++) {
            mma16(acc1[0][nt], aH4[0], bf[nt]);
            mma16(acc1[1][nt], aH4[1], bf[nt]);
        }
    }
#pragma unroll
    for (int m = 0; m < 2; m++)
#pragma unroll
        for (int nt = 0; nt < 4; nt++)
#pragma unroll
            for (int k = 0; k < 4; k++) acc2[m][nt][k] = acc1[m][nt][k];

    // Head part: WT kw [0,32): src words [0,32) -> acc1, dst words [32,64) -> acc2
    for (int ks = 0; ks < 4; ks++) {
        uint32_t aS4[2][4], aD4[2][4];
        uint32_t bf[4][2];
        ldB4h(bf, WTbase + ks * 8);
        ldA(aS4[0], A, AS, 0, ks * 8, g, t4);
        ldA(aS4[1], A, AS, 16, ks * 8, g, t4);
        ldA(aD4[0], A, AS, 0, 32 + ks * 8, g, t4);
        ldA(aD4[1], A, AS, 16, 32 + ks * 8, g, t4);
#pragma unroll
        for (int nt = 0; nt < 4; nt++) {
            mma16(acc1[0][nt], aS4[0], bf[nt]);
            mma16(acc1[1][nt], aS4[1], bf[nt]);
            mma16(acc2[0][nt], aD4[0], bf[nt]);
            mma16(acc2[1][nt], aD4[1], bf[nt]);
        }
    }

    // Stage into smem (f32), then coalesced writeback (half out + f32 sum2 red)
    __syncthreads();
    float* Ss = (float*)sm;
    float* Sd = (float*)sm + 32 * 128;
#pragma unroll
    for (int m = 0; m < 2; m++)
#pragma unroll
        for (int h = 0; h < 2; h++) {
            int r = m * 16 + h * 8 + g;
            int key = (r & 7) << 2;
#pragma unroll
            for (int nt = 0; nt < 4; nt++) {
                int col = (ntB + nt) * 8 + t4 * 2;
                float2 vs = make_float2(acc1[m][nt][h * 2 + 0], acc1[m][nt][h * 2 + 1]);
                float2 vd = make_float2(acc2[m][nt][h * 2 + 0], acc2[m][nt][h * 2 + 1]);
                *(float2*)&Ss[r * 128 + (col ^ key)] = vs;
                *(float2*)&Sd[r * 128 + (col ^ key)] = vd;
            }
        }
    __syncthreads();
    for (int i = tid; i < 32 * 32; i += 128) {
        int r = i >> 5, q = (i & 31) * 4;
        int e = e0 + r;
        if (e < E) {
            int key = (r & 7) << 2;
            int s = sI[r], d = dI[r];
            float4 vs = *(float4*)&Ss[r * 128 + (q ^ key)];
            float4 vd = *(float4*)&Sd[r * 128 + (q ^ key)];
            float4 bb = ldg4(&bias[q]);
            float4 ps = ldg4(&proj[(size_t)s * 128 + q]);
            float4 pd = ldg4(&proj[(size_t)d * 128 + q]);
            float4 os, od;
            os.x = fmaxf(vs.x + bb.x + ps.x, 0.f);
            os.y = fmaxf(vs.y + bb.y + ps.y, 0.f);
            os.z = fmaxf(vs.z + bb.z + ps.z, 0.f);
            os.w = fmaxf(vs.w + bb.w + ps.w, 0.f);
            od.x = fmaxf(vd.x + bb.x + pd.x, 0.f);
            od.y = fmaxf(vd.y + bb.y + pd.y, 0.f);
            od.z = fmaxf(vd.z + bb.z + pd.z, 0.f);
            od.w = fmaxf(vd.w + bb.w + pd.w, 0.f);
            uint2 hs, hd;
            hs.x = packh2(os.x, os.y); hs.y = packh2(os.z, os.w);
            hd.x = packh2(od.x, od.y); hd.y = packh2(od.z, od.w);
            *(uint2*)&outS[(size_t)e * 128 + q] = hs;
            *(uint2*)&outD[(size_t)e * 128 + q] = hd;
            red4(&sum2[(size_t)s * 128 + q], od);
            red4(&sum2[(size_t)d * 128 + q], os);
        }
    }
}

// ---------------------------------------------------------------------------
// fp16 tensor-core layer-2 edge kernel.
// A words (stride 160): [0,64)=srcF, [64,128)=dstF, [128,160)=te2
// WT kw: head [0,64), te [64,96). Writes final f32 output.
// ---------------------------------------------------------------------------
__global__ __launch_bounds__(128, 4) void k_layer2_t(
    const __half* __restrict__ fS, const __half* __restrict__ fD,
    const int* __restrict__ src, const int* __restrict__ dst, const float* __restrict__ ts,
    const uint32_t* __restrict__ WT, const float* __restrict__ bias,
    const float* __restrict__ omega, const float* __restrict__ phase,
    const float* __restrict__ proj, float* __restrict__ outS, float* __restrict__ outD, int E) {
    const int AS = 160;  // words per edge row
    extern __shared__ uint32_t sm[];
    uint32_t* A = sm;    // 32*160 words = 20KB; staging 32KB (smem = 32KB)
    __shared__ int sI[32], dI[32];
    int tid = threadIdx.x, lane = tid & 31, warp = tid >> 5;
    int g = lane >> 2, t4 = lane & 3;
    int e0 = blockIdx.x * 32;
    int ntB = warp * 4;

    if (tid < 32) {
        int e = e0 + tid;
        bool ok = e < E;
        sI[tid] = ok ? __ldg(&src[e]) : 0;
        dI[tid] = ok ? __ldg(&dst[e]) : 0;
    }
    __syncthreads();

    // Fill A: raw half copy of srcF/dstF rows (16 uint4 each per edge)
    for (int i = tid; i < 32 * 32; i += 128) {
        int r = i >> 5, p = i & 31;
        int e = e0 + r;
        bool ok = e < E;
        uint4 v = make_uint4(0, 0, 0, 0);
        int wcol;
        if (p < 16) {
            wcol = p * 4;
            if (ok) v = *(const uint4*)&fS[(size_t)e * 128 + p * 8];
        } else {
            wcol = 64 + (p - 16) * 4;
            if (ok) v = *(const uint4*)&fD[(size_t)e * 128 + (p - 16) * 8];
        }
        *(uint4*)&A[r * AS + (wcol ^ ((r & 7) << 2))] = v;
    }
    // te2: half cols -> words [128,160)
    for (int i = tid; i < 32 * 16; i += 128) {
        int r = i >> 4, q = (i & 15) * 4;
        int e = e0 + r;
        float t = (e < E) ? __ldg(&ts[e]) : 0.f;
        float c0 = cosf(t * __ldg(&omega[q + 0]) + __ldg(&phase[q + 0]));
        float c1 = cosf(t * __ldg(&omega[q + 1]) + __ldg(&phase[q + 1]));
        float c2 = cosf(t * __ldg(&omega[q + 2]) + __ldg(&phase[q + 2]));
        float c3 = cosf(t * __ldg(&omega[q + 3]) + __ldg(&phase[q + 3]));
        uint2 u;
        u.x = packh2(c0, c1);
        u.y = packh2(c2, c3);
        *(uint2*)&A[r * AS + ((128 + (q >> 1)) ^ ((r & 7) << 2))] = u;
    }
    __syncthreads();

    float acc1[2][4][4], acc2[2][4][4];
#pragma unroll
    for (int m = 0; m < 2; m++)
#pragma unroll
        for (int nt = 0; nt < 4; nt++)
#pragma unroll
            for (int k = 0; k < 4; k++) acc1[m][nt][k] = 0.f;

    const uint32_t* WTbase = WT + (size_t)(ntB * 8 + g) * 96 + t4;

    // Shared te part: A words [128,160), WT kw [64,96): 4 k16 steps -> acc1
    for (int ks = 0; ks < 4; ks++) {
        uint32_t aH4[2][4];
        uint32_t bf[4][2];
        ldB4h(bf, WTbase + 64 + ks * 8);
        ldA(aH4[0], A, AS, 0, 128 + ks * 8, g, t4);
        ldA(aH4[1], A, AS, 16, 128 + ks * 8, g, t4);
#pragma unroll
        for (int nt = 0; nt < 4; nt++) {
            mma16(acc1[0][nt], aH4[0], bf[nt]);
            mma16(acc1[1][nt], aH4[1], bf[nt]);
        }
    }
#pragma unroll
    for (int m = 0; m < 2; m++)
#pragma unroll
        for (int nt = 0; nt < 4; nt++)
#pragma unroll
            for (int k = 0; k < 4; k++) acc2[m][nt][k] = acc1[m][nt][k];

    // Head: WT kw [0,64): src words [0,64) -> acc1, dst words [64,128) -> acc2
    for (int ks = 0; ks < 8; ks++) {
        uint32_t aS4[2][4], aD4[2][4];
        uint32_t bf[4][2];
        ldB4h(bf, WTbase + ks * 8);
        ldA(aS4[0], A, AS, 0, ks * 8, g, t4);
        ldA(aS4[1], A, AS, 16, ks * 8, g, t4);
        ldA(aD4[0], A, AS, 0, 64 + ks * 8, g, t4);
        ldA(aD4[1], A, AS, 16, 64 + ks * 8, g, t4);
#pragma unroll
        for (int nt = 0; nt < 4; nt++) {
            mma16(acc1[0][nt], aS4[0], bf[nt]);
            mma16(acc1[1][nt], aS4[1], bf[nt]);
            mma16(acc2[0][nt], aD4[0], bf[nt]);
            mma16(acc2[1][nt], aD4[1], bf[nt]);
        }
    }

    // Stage + coalesced f32 writeback
    __syncthreads();
    float* Ss = (float*)sm;
    float* Sd = (float*)sm + 32 * 128;
#pragma unroll
    for (int m = 0; m < 2; m++)
#pragma unroll
        for (int h = 0; h < 2; h++) {
            int r = m * 16 + h * 8 + g;
            int key = (r & 7) << 2;
#pragma unroll
            for (int nt = 0; nt < 4; nt++) {
                int col = (ntB + nt) * 8 + t4 * 2;
                float2 vs = make_float2(acc1[m][nt][h * 2 + 0], acc1[m][nt][h * 2 + 1]);
                float2 vd = make_float2(acc2[m][nt][h * 2 + 0], acc2[m][nt][h * 2 + 1]);
                *(float2*)&Ss[r * 128 + (col ^ key)] = vs;
                *(float2*)&Sd[r * 128 + (col ^ key)] = vd;
            }
        }
    __syncthreads();
    for (int i = tid; i < 32 * 32; i += 128) {
        int r = i >> 5, q = (i & 31) * 4;
        int e = e0 + r;
        if (e < E) {
            int key = (r & 7) << 2;
            int s = sI[r], d = dI[r];
            float4 vs = *(float4*)&Ss[r * 128 + (q ^ key)];
            float4 vd = *(float4*)&Sd[r * 128 + (q ^ key)];
            float4 bb = ldg4(&bias[q]);
            float4 ps = ldg4(&proj[(size_t)s * 128 + q]);
            float4 pd = ldg4(&proj[(size_t)d * 128 + q]);
            float4 os, od;
            os.x = fmaxf(vs.x + bb.x + ps.x, 0.f);
            os.y = fmaxf(vs.y + bb.y + ps.y, 0.f);
            os.z = fmaxf(vs.z + bb.z + ps.z, 0.f);
            os.w = fmaxf(vs.w + bb.w + ps.w, 0.f);
            od.x = fmaxf(vd.x + bb.x + pd.x, 0.f);
            od.y = fmaxf(vd.y + bb.y + pd.y, 0.f);
            od.z = fmaxf(vd.z + bb.z + pd.z, 0.f);
            od.w = fmaxf(vd.w + bb.w + pd.w, 0.f);
            *(float4*)&outS[(size_t)e * 128 + q] = os;
            *(float4*)&outD[(size_t)e * 128 + q] = od;
        }
    }
}

// ---------------------------------------------------------------------------
extern "C" void kernel_launch(void* const* d_in, const int* in_sizes, int n_in,
                              void* d_out, int out_size) {
    const float* nfeat = (const float*)d_in[0];
    const float* efeat = (const float*)d_in[1];
    const int*   src   = (const int*)d_in[2];
    const int*   dst   = (const int*)d_in[3];
    const float* ts    = (const float*)d_in[4];
    const float* Ws1 = (const float*)d_in[5];
    const float* bs1 = (const float*)d_in[6];
    const float* Wn1 = (const float*)d_in[7];
    const float* bn1 = (const float*)d_in[8];
    const float* om1 = (const float*)d_in[9];
    const float* ph1 = (const float*)d_in[10];
    const float* Ws2 = (const float*)d_in[11];
    const float* bs2 = (const float*)d_in[12];
    const float* Wn2 = (const float*)d_in[13];
    const float* bn2 = (const float*)d_in[14];
    const float* om2 = (const float*)d_in[15];
    const float* ph2 = (const float*)d_in[16];

    int Nn = in_sizes[0] / 64;
    int E  = in_sizes[2];

    float *cnt, *s1, *s2, *proj;
    __half *sf, *df;
    uint32_t *wt1, *wt2;
    cudaGetSymbolAddress((void**)&cnt,  g_cnt);
    cudaGetSymbolAddress((void**)&s1,   g_sum1);
    cudaGetSymbolAddress((void**)&s2,   g_sum2);
    cudaGetSymbolAddress((void**)&proj, g_proj);
    cudaGetSymbolAddress((void**)&sf,   g_srcF);
    cudaGetSymbolAddress((void**)&df,   g_dstF);
    cudaGetSymbolAddress((void**)&wt1,  g_WT1);
    cudaGetSymbolAddress((void**)&wt2,  g_WT2);

    float* outv = (float*)d_out;
    int nTileBlocks = (Nn + 31) / 32;
    int eTileBlocks = (E + 31) / 32;

    size_t smProj = (size_t)(32 * 128) * 4;   // 16 KB
    size_t smL    = (size_t)(64 * 128) * 4;   // 32 KB (A-tile + staging superset)

    cudaFuncSetAttribute(k_proj_t,   cudaFuncAttributeMaxDynamicSharedMemorySize, (int)smProj);
    cudaFuncSetAttribute(k_layer1_t, cudaFuncAttributeMaxDynamicSharedMemorySize, (int)smL);
    cudaFuncSetAttribute(k_layer2_t, cudaFuncAttributeMaxDynamicSharedMemorySize, (int)smL);

    k_prepW<<<48, 256>>>(Ws1, Ws2, wt1, wt2);
    k_zero<<<2048, 256>>>(cnt, s1, s2, Nn);
    k_agg1<<<2048, 256>>>(nfeat, efeat, src, dst, s1, cnt, E);
    k_proj_t<<<nTileBlocks, 128, smProj>>>(s1, cnt, Wn1, bn1, proj, Nn);
    k_layer1_t<<<eTileBlocks, 128, smL>>>(nfeat, efeat, src, dst, ts, wt1, bs1, om1, ph1,
                                          proj, sf, df, s2, E);
    k_proj_t<<<nTileBlocks, 128, smProj>>>(s2, cnt, Wn2, bn2, proj, Nn);
    k_layer2_t<<<eTileBlocks, 128, smL>>>(sf, df, src, dst, ts, wt2, bs2, om2, ph2,
                                          proj, outv, outv + (size_t)E * 128, E);
}